// round 12
// baseline (speedup 1.0000x reference)
#include <cuda_runtime.h>
#include <cstdint>
#include <math.h>

#define BD   2
#define SD   2048
#define DD   1024
#define HH   16
#define DHH  64
#define FFD  4096
#define NR   (BD*SD)              // 4096 rows
#define QKVD 3072
#define NEGV (-1000000000.0f)

// ---------------- scratch (static device globals; no allocation allowed) ----
__device__ float g_x   [NR*DD];             // fp32 residual stream
__device__ float g_xt  [NR*DD];             // tf32 shadow of LN1 out
__device__ float g_qkv [(size_t)NR*QKVD];   // fused Q|K|V, tf32 bits
__device__ float g_att [NR*DD];             // tf32 bits
__device__ float g_ao  [NR*DD];             // fp32
__device__ float g_xn  [NR*DD];             // tf32 bits (LN3 out)
__device__ float g_h   [(size_t)NR*FFD];    // tf32 bits (gelu out)
__device__ float g_pad [NR];
__device__ float g_wqkv[(size_t)QKVD*DD];   // tf32 bits
__device__ float g_bqkv[QKVD];
__device__ float g_wo  [DD*DD];             // tf32 bits
__device__ float g_w1  [(size_t)DD*FFD];    // tf32 bits
__device__ float g_w2  [(size_t)DD*FFD];    // tf32 bits

// ---------------- tf32 / mma helpers ----------------------------------------
__device__ __forceinline__ float gelu_f(float x) {
    return 0.5f * x * (1.0f + erff(x * 0.70710678118654752f));
}
__device__ __forceinline__ uint32_t f2tf32(float x) {
    uint32_t t;
    asm("cvt.rna.tf32.f32 %0, %1;" : "=r"(t) : "f"(x));
    return t;
}
__device__ __forceinline__ void mma1688(float* c, const uint32_t* a, const uint32_t* b) {
    asm volatile(
        "mma.sync.aligned.m16n8k8.row.col.f32.tf32.tf32.f32 "
        "{%0,%1,%2,%3}, {%4,%5,%6,%7}, {%8,%9}, {%0,%1,%2,%3};"
        : "+f"(c[0]), "+f"(c[1]), "+f"(c[2]), "+f"(c[3])
        : "r"(a[0]), "r"(a[1]), "r"(a[2]), "r"(a[3]), "r"(b[0]), "r"(b[1]));
}
__device__ __forceinline__ uint32_t smem_u32(const void* p) {
    uint32_t a;
    asm("{ .reg .u64 t; cvta.to.shared.u64 t, %1; cvt.u32.u64 %0, t; }"
        : "=r"(a) : "l"(p));
    return a;
}
#define LDSM4(r0, r1, r2, r3, addr) \
    asm volatile("ldmatrix.sync.aligned.m8n8.x4.shared.b16 {%0,%1,%2,%3}, [%4];" \
                 : "=r"(r0), "=r"(r1), "=r"(r2), "=r"(r3) : "r"(addr))

// ---------------- block-wide sum over 256 threads ---------------------------
__device__ __forceinline__ float blockSum(float v, float* sm) {
    int lane = threadIdx.x & 31;
    #pragma unroll
    for (int o = 16; o; o >>= 1) v += __shfl_xor_sync(0xffffffffu, v, o);
    if (lane == 0) sm[threadIdx.x >> 5] = v;
    __syncthreads();
    float t = sm[lane & 7];
    #pragma unroll
    for (int o = 4; o; o >>= 1) t += __shfl_xor_sync(0xffffffffu, t, o);
    __syncthreads();
    return t;
}

// ---------------- K1: embedding + pos + LN1 -> g_x, g_xt ; pad mask ---------
__global__ void embed_ln_k(const int* __restrict__ tok,
                           const float* __restrict__ emb,
                           const float* __restrict__ pos,
                           const float* __restrict__ gam,
                           const float* __restrict__ bet) {
    __shared__ float sm[8];
    int n = blockIdx.x;
    int t = tok[n];
    int s = n & (SD - 1);
    int c0 = threadIdx.x * 4;
    float4 e = *(const float4*)(emb + (size_t)t * DD + c0);
    float4 p = *(const float4*)(pos + (size_t)s * DD + c0);
    float v0 = e.x + p.x, v1 = e.y + p.y, v2 = e.z + p.z, v3 = e.w + p.w;
    float mean = blockSum(v0 + v1 + v2 + v3, sm) * (1.0f / DD);
    float d0 = v0 - mean, d1 = v1 - mean, d2 = v2 - mean, d3 = v3 - mean;
    float var = blockSum(d0*d0 + d1*d1 + d2*d2 + d3*d3, sm) * (1.0f / DD);
    float rs = rsqrtf(var + 1e-5f);
    float4 gg = *(const float4*)(gam + c0);
    float4 bb = *(const float4*)(bet + c0);
    float4 o;
    o.x = d0 * rs * gg.x + bb.x;
    o.y = d1 * rs * gg.y + bb.y;
    o.z = d2 * rs * gg.z + bb.z;
    o.w = d3 * rs * gg.w + bb.w;
    *(float4*)(g_x + (size_t)n * DD + c0) = o;
    uint4 ot = make_uint4(f2tf32(o.x), f2tf32(o.y), f2tf32(o.z), f2tf32(o.w));
    *(uint4*)(g_xt + (size_t)n * DD + c0) = ot;
    if (threadIdx.x == 0) g_pad[n] = (t == 0) ? NEGV : 0.0f;
}

// -------- fused LN2+LN3: g_x += LN2(g_ao); g_xn = tf32(LN3(g_x)) ------------
__global__ void ln23_k(const float* __restrict__ g2, const float* __restrict__ b2v,
                       const float* __restrict__ g3, const float* __restrict__ b3v) {
    __shared__ float sm[8];
    int n = blockIdx.x;
    int c0 = threadIdx.x * 4;
    float4 av = *(const float4*)(g_ao + (size_t)n * DD + c0);
    float mean = blockSum(av.x + av.y + av.z + av.w, sm) * (1.0f / DD);
    float d0 = av.x - mean, d1 = av.y - mean, d2 = av.z - mean, d3 = av.w - mean;
    float var = blockSum(d0*d0 + d1*d1 + d2*d2 + d3*d3, sm) * (1.0f / DD);
    float rs = rsqrtf(var + 1e-5f);
    float4 gg = *(const float4*)(g2 + c0);
    float4 bb = *(const float4*)(b2v + c0);
    float4 x = *(float4*)(g_x + (size_t)n * DD + c0);
    x.x += d0 * rs * gg.x + bb.x;
    x.y += d1 * rs * gg.y + bb.y;
    x.z += d2 * rs * gg.z + bb.z;
    x.w += d3 * rs * gg.w + bb.w;
    *(float4*)(g_x + (size_t)n * DD + c0) = x;
    float mean3 = blockSum(x.x + x.y + x.z + x.w, sm) * (1.0f / DD);
    float e0 = x.x - mean3, e1 = x.y - mean3, e2 = x.z - mean3, e3 = x.w - mean3;
    float var3 = blockSum(e0*e0 + e1*e1 + e2*e2 + e3*e3, sm) * (1.0f / DD);
    float rs3 = rsqrtf(var3 + 1e-5f);
    float4 g3v = *(const float4*)(g3 + c0);
    float4 b3f = *(const float4*)(b3v + c0);
    uint4 o = make_uint4(f2tf32(e0 * rs3 * g3v.x + b3f.x),
                         f2tf32(e1 * rs3 * g3v.y + b3f.y),
                         f2tf32(e2 * rs3 * g3v.z + b3f.z),
                         f2tf32(e3 * rs3 * g3v.w + b3f.w));
    *(uint4*)(g_xn + (size_t)n * DD + c0) = o;
}

// ------- weight transpose + tf32 pre-round: out[C,R] = tf32(in[R,C]^T) ------
__global__ void transpose_k(const float* __restrict__ in, float* __restrict__ out,
                            int R, int Cc) {
    __shared__ float t[32][33];
    int bx = blockIdx.x * 32, by = blockIdx.y * 32;
    int x = bx + threadIdx.x;
    #pragma unroll
    for (int i = 0; i < 4; i++)
        t[threadIdx.y + i * 8][threadIdx.x] = in[(size_t)(by + threadIdx.y + i * 8) * Cc + x];
    __syncthreads();
    int xo = by + threadIdx.x;
    #pragma unroll
    for (int i = 0; i < 4; i++)
        out[(size_t)(bx + threadIdx.y + i * 8) * R + xo] =
            __uint_as_float(f2tf32(t[threadIdx.x][threadIdx.y + i * 8]));
}

// ---- merged QKV+Wo transpose (blockIdx.z selects; all DDxDD) ---------------
__global__ void transpose_qkvo_k(const float* __restrict__ Wq,
                                 const float* __restrict__ Wk,
                                 const float* __restrict__ Wv,
                                 const float* __restrict__ Wo) {
    __shared__ float t[32][33];
    const float* in = (blockIdx.z == 0) ? Wq : (blockIdx.z == 1) ? Wk
                    : (blockIdx.z == 2) ? Wv : Wo;
    float* out = (blockIdx.z < 3) ? (g_wqkv + (size_t)blockIdx.z * DD * DD) : g_wo;
    int bx = blockIdx.x * 32, by = blockIdx.y * 32;
    int x = bx + threadIdx.x;
    #pragma unroll
    for (int i = 0; i < 4; i++)
        t[threadIdx.y + i * 8][threadIdx.x] = in[(size_t)(by + threadIdx.y + i * 8) * DD + x];
    __syncthreads();
    int xo = by + threadIdx.x;
    #pragma unroll
    for (int i = 0; i < 4; i++)
        out[(size_t)(bx + threadIdx.y + i * 8) * DD + xo] =
            __uint_as_float(f2tf32(t[threadIdx.x][threadIdx.y + i * 8]));
}

// ---------------- bias pack: g_bqkv = [bq | bk | bv] ------------------------
__global__ void pack_bias_k(const float* __restrict__ bq,
                            const float* __restrict__ bk,
                            const float* __restrict__ bv) {
    int i = blockIdx.x * 256 + threadIdx.x;
    float v = (i < 1024) ? bq[i] : (i < 2048) ? bk[i - 1024] : bv[i - 2048];
    g_bqkv[i] = v;
}

// ------ mma.sync tf32 GEMM, double-buffered LDG prefetch + ldmatrix ---------
// EPI 0: +bias fp32   EPI 1: gelu -> tf32   EPI 2: +bias+res fp32
// EPI 3: +bias -> tf32
#define SSTR 36
#define SBUF (128 * SSTR)                  // uint32 per operand per stage
#define GEMM_SMEM (2 * 2 * SBUF * 4)       // 73728 bytes

template <int EPI>
__global__ __launch_bounds__(256, 2)
void tc_gemm(const float* __restrict__ A, const float* __restrict__ Bt,
             const float* __restrict__ bias, float* __restrict__ C,
             int K, int Mout, const float* __restrict__ res) {
    extern __shared__ uint32_t dsm[];

    int tid  = threadIdx.x;
    int wid  = tid >> 5;
    int lane = tid & 31;
    int wm   = wid >> 1;
    int wn   = wid & 1;
    int gq   = lane >> 2;
    int tg   = lane & 3;

    int r  = tid >> 1;
    int cb = (tid & 1) * 16;
    const float* ArowP = A  + (size_t)(blockIdx.y * 128 + r) * K + cb;
    const float* BrowP = Bt + (size_t)(blockIdx.x * 128 + r) * K + cb;
    uint32_t rowoff = r * SSTR + cb;
    uint32_t sbase = smem_u32(dsm);

    uint32_t aoffB[2], boffB[4];
    #pragma unroll
    for (int mt = 0; mt < 2; mt++)
        aoffB[mt] = ((wm * 32 + mt * 16 + (lane & 15)) * SSTR + ((lane >> 4) << 2)) * 4;
    #pragma unroll
    for (int p = 0; p < 4; p++)
        boffB[p] = (SBUF + (wn * 64 + p * 16 + ((lane >> 4) << 3) + (lane & 7)) * SSTR
                    + (((lane >> 3) & 1) << 2)) * 4;

    float acc[2][8][4];
    #pragma unroll
    for (int mt = 0; mt < 2; mt++)
        #pragma unroll
        for (int nt = 0; nt < 8; nt++)
            #pragma unroll
            for (int c = 0; c < 4; c++) acc[mt][nt][c] = 0.0f;

    int NC = K >> 5;
    uint4 pa[4], pb[4];
    #pragma unroll
    for (int q = 0; q < 4; q++) {
        pa[q] = *(const uint4*)(ArowP + q * 4);
        pb[q] = *(const uint4*)(BrowP + q * 4);
    }
    {
        uint32_t* dA = dsm + rowoff;
        uint32_t* dB = dA + SBUF;
        #pragma unroll
        for (int q = 0; q < 4; q++) {
            *(uint4*)(dA + q * 4) = pa[q];
            *(uint4*)(dB + q * 4) = pb[q];
        }
    }
    __syncthreads();

    for (int i = 0; i < NC; i++) {
        uint32_t bufbase = sbase + (i & 1) * (2 * SBUF * 4);
        if (i + 1 < NC) {
            #pragma unroll
            for (int q = 0; q < 4; q++) {
                pa[q] = *(const uint4*)(ArowP + (i + 1) * 32 + q * 4);
                pb[q] = *(const uint4*)(BrowP + (i + 1) * 32 + q * 4);
            }
        }
        #pragma unroll
        for (int ks = 0; ks < 4; ks++) {
            uint32_t kb = ks * 32;
            uint32_t af[2][4], bf[8][2];
            LDSM4(af[0][0], af[0][1], af[0][2], af[0][3], bufbase + aoffB[0] + kb);
            LDSM4(af[1][0], af[1][1], af[1][2], af[1][3], bufbase + aoffB[1] + kb);
            LDSM4(bf[0][0], bf[0][1], bf[1][0], bf[1][1], bufbase + boffB[0] + kb);
            LDSM4(bf[2][0], bf[2][1], bf[3][0], bf[3][1], bufbase + boffB[1] + kb);
            LDSM4(bf[4][0], bf[4][1], bf[5][0], bf[5][1], bufbase + boffB[2] + kb);
            LDSM4(bf[6][0], bf[6][1], bf[7][0], bf[7][1], bufbase + boffB[3] + kb);
            #pragma unroll
            for (int mt = 0; mt < 2; mt++)
                #pragma unroll
                for (int nt = 0; nt < 8; nt++)
                    mma1688(acc[mt][nt], af[mt], bf[nt]);
        }
        if (i + 1 < NC) {
            uint32_t* dA = dsm + ((i + 1) & 1) * 2 * SBUF + rowoff;
            uint32_t* dB = dA + SBUF;
            #pragma unroll
            for (int q = 0; q < 4; q++) {
                *(uint4*)(dA + q * 4) = pa[q];
                *(uint4*)(dB + q * 4) = pb[q];
            }
        }
        __syncthreads();
    }

    #pragma unroll
    for (int mt = 0; mt < 2; mt++) {
        #pragma unroll
        for (int nt = 0; nt < 8; nt++) {
            int col = blockIdx.x * 128 + wn * 64 + nt * 8 + 2 * tg;
            float2 bb = *(const float2*)(bias + col);
            #pragma unroll
            for (int h = 0; h < 2; h++) {
                int row = blockIdx.y * 128 + wm * 32 + mt * 16 + gq + h * 8;
                size_t off = (size_t)row * Mout + col;
                float2 o;
                o.x = acc[mt][nt][2 * h + 0] + bb.x;
                o.y = acc[mt][nt][2 * h + 1] + bb.y;
                if (EPI == 1) { o.x = gelu_f(o.x); o.y = gelu_f(o.y); }
                if (EPI == 2) {
                    float2 rr = *(const float2*)(res + off);
                    o.x += rr.x; o.y += rr.y;
                }
                if (EPI == 1 || EPI == 3) {
                    o.x = __uint_as_float(f2tf32(o.x));
                    o.y = __uint_as_float(f2tf32(o.y));
                }
                *(float2*)(C + off) = o;
            }
        }
    }
}

// ---------------- tensor-core flash attention (tf32) ------------------------
// 128 queries/CTA, 8 warps x 16 queries, key tiles 64, ping-pong K/V buffers.
#define ASTR 68
#define ATB  (64 * ASTR)                    // uint32 per K (or V) buffer
#define ATTN_SMEM (2 * 2 * ATB * 4)         // 69632 bytes

__device__ __forceinline__ void quad_permute(uint32_t p0, uint32_t p1, int lane,
                                             uint32_t& a_lo, uint32_t& a_hi) {
    int tg = lane & 3;
    int base = lane & ~3;
    int l1 = base + (tg >> 1);
    int l2 = base + 2 + (tg >> 1);
    uint32_t s0a = __shfl_sync(0xffffffffu, p0, l1);
    uint32_t s1a = __shfl_sync(0xffffffffu, p1, l1);
    uint32_t s0b = __shfl_sync(0xffffffffu, p0, l2);
    uint32_t s1b = __shfl_sync(0xffffffffu, p1, l2);
    a_lo = (tg & 1) ? s1a : s0a;
    a_hi = (tg & 1) ? s1b : s0b;
}

__global__ __launch_bounds__(256)
void attn_tc() {
    extern __shared__ uint32_t asmem[];     // [buf][K|V][64*ASTR]
    __shared__ float sPad[2][64];

    int qt = (gridDim.x - 1) - blockIdx.x;  // longest CTAs first
    int bh = blockIdx.y;
    int b = bh >> 4, h = bh & 15;
    int tid = threadIdx.x;
    int w = tid >> 5, lane = tid & 31;
    int gq = lane >> 2, tg = lane & 3;
    int qabs0 = qt * 128 + w * 16;

    // Q fragments (g_qkv already tf32 bits)
    uint32_t qa[8][4];
    const float* Qb = g_qkv + ((size_t)(b * SD) + qabs0) * QKVD + h * DHH;
    #pragma unroll
    for (int ks = 0; ks < 8; ks++) {
        qa[ks][0] = __float_as_uint(Qb[(size_t)gq * QKVD + ks * 8 + tg]);
        qa[ks][1] = __float_as_uint(Qb[(size_t)(gq + 8) * QKVD + ks * 8 + tg]);
        qa[ks][2] = __float_as_uint(Qb[(size_t)gq * QKVD + ks * 8 + tg + 4]);
        qa[ks][3] = __float_as_uint(Qb[(size_t)(gq + 8) * QKVD + ks * 8 + tg + 4]);
    }

    float m0 = -1e30f, m1 = -1e30f, l0 = 0.0f, l1 = 0.0f;
    float Oa[8][4];
    #pragma unroll
    for (int nt = 0; nt < 8; nt++)
        #pragma unroll
        for (int c = 0; c < 4; c++) Oa[nt][c] = 0.0f;

    int lr = tid >> 2;              // 0..63
    int lc = (tid & 3) * 16;        // 0,16,32,48
    uint32_t stoff = (uint32_t)(lr * ASTR + lc);

    int KBMAX = 2 * qt + 1;
    // prologue: stage tile 0 into buffer 0
    {
        size_t gb = ((size_t)(b * SD) + lr) * QKVD + h * DHH + lc;
        #pragma unroll
        for (int q = 0; q < 4; q++) {
            *(uint4*)(asmem + stoff + q * 4)       = *(const uint4*)(g_qkv + gb + 1024 + q * 4);
            *(uint4*)(asmem + ATB + stoff + q * 4) = *(const uint4*)(g_qkv + gb + 2048 + q * 4);
        }
        if (tid < 64) sPad[0][tid] = g_pad[(size_t)b * SD + tid];
    }
    __syncthreads();

    for (int kb = 0; kb <= KBMAX; kb++) {
        int cur = kb & 1;
        // stage NEXT tile into the other buffer (overlaps compute below)
        if (kb < KBMAX) {
            int nxt = cur ^ 1;
            size_t gb = ((size_t)(b * SD) + (kb + 1) * 64 + lr) * QKVD + h * DHH + lc;
            uint32_t* dst = asmem + nxt * 2 * ATB + stoff;
            #pragma unroll
            for (int q = 0; q < 4; q++) {
                *(uint4*)(dst + q * 4)       = *(const uint4*)(g_qkv + gb + 1024 + q * 4);
                *(uint4*)(dst + ATB + q * 4) = *(const uint4*)(g_qkv + gb + 2048 + q * 4);
            }
            if (tid < 64) sPad[nxt][tid] = g_pad[(size_t)b * SD + (kb + 1) * 64 + tid];
        }

        if (kb * 64 <= qabs0 + 15) {            // warp-uniform causal skip
            const uint32_t* sK = asmem + cur * 2 * ATB;
            const uint32_t* sV = sK + ATB;
            float sv[8][4];
            #pragma unroll
            for (int nt = 0; nt < 8; nt++)
                #pragma unroll
                for (int c = 0; c < 4; c++) sv[nt][c] = 0.0f;
            #pragma unroll
            for (int ks = 0; ks < 8; ks++) {
                #pragma unroll
                for (int nt = 0; nt < 8; nt++) {
                    const uint32_t* kp = sK + (nt * 8 + gq) * ASTR + ks * 8 + tg;
                    uint32_t bk[2] = { kp[0], kp[4] };
                    mma1688(sv[nt], qa[ks], bk);
                }
            }
            int q0 = qabs0 + gq, q1 = q0 + 8;
            float mx0 = -1e30f, mx1 = -1e30f;
            #pragma unroll
            for (int nt = 0; nt < 8; nt++) {
                int kc = kb * 64 + nt * 8 + 2 * tg;
                float pad0 = sPad[cur][nt * 8 + 2 * tg];
                float pad1 = sPad[cur][nt * 8 + 2 * tg + 1];
                sv[nt][0] = sv[nt][0] * 0.125f + pad0 + ((kc     > q0) ? NEGV : 0.0f);
                sv[nt][1] = sv[nt][1] * 0.125f + pad1 + ((kc + 1 > q0) ? NEGV : 0.0f);
                sv[nt][2] = sv[nt][2] * 0.125f + pad0 + ((kc     > q1) ? NEGV : 0.0f);
                sv[nt][3] = sv[nt][3] * 0.125f + pad1 + ((kc + 1 > q1) ? NEGV : 0.0f);
                mx0 = fmaxf(mx0, fmaxf(sv[nt][0], sv[nt][1]));
                mx1 = fmaxf(mx1, fmaxf(sv[nt][2], sv[nt][3]));
            }
            mx0 = fmaxf(mx0, __shfl_xor_sync(0xffffffffu, mx0, 1));
            mx0 = fmaxf(mx0, __shfl_xor_sync(0xffffffffu, mx0, 2));
            mx1 = fmaxf(mx1, __shfl_xor_sync(0xffffffffu, mx1, 1));
            mx1 = fmaxf(mx1, __shfl_xor_sync(0xffffffffu, mx1, 2));
            float mn0 = fmaxf(m0, mx0), mn1 = fmaxf(m1, mx1);
            float cr0 = __expf(m0 - mn0), cr1 = __expf(m1 - mn1);
            m0 = mn0; m1 = mn1;

            float rs0 = 0.0f, rs1 = 0.0f;
            uint32_t pfr[8][4];
            #pragma unroll
            for (int nt = 0; nt < 8; nt++) {
                float p0 = __expf(sv[nt][0] - mn0);
                float p1 = __expf(sv[nt][1] - mn0);
                float p2 = __expf(sv[nt][2] - mn1);
                float p3 = __expf(sv[nt][3] - mn1);
                rs0 += p0 + p1; rs1 += p2 + p3;
                quad_permute(f2tf32(p0), f2tf32(p1), lane, pfr[nt][0], pfr[nt][2]);
                quad_permute(f2tf32(p2), f2tf32(p3), lane, pfr[nt][1], pfr[nt][3]);
            }
            rs0 += __shfl_xor_sync(0xffffffffu, rs0, 1);
            rs0 += __shfl_xor_sync(0xffffffffu, rs0, 2);
            rs1 += __shfl_xor_sync(0xffffffffu, rs1, 1);
            rs1 += __shfl_xor_sync(0xffffffffu, rs1, 2);
            l0 = l0 * cr0 + rs0;
            l1 = l1 * cr1 + rs1;
            #pragma unroll
            for (int nt = 0; nt < 8; nt++) {
                Oa[nt][0] *= cr0; Oa[nt][1] *= cr0;
                Oa[nt][2] *= cr1; Oa[nt][3] *= cr1;
            }
            #pragma unroll
            for (int ks = 0; ks < 8; ks++) {
                #pragma unroll
                for (int nt = 0; nt < 8; nt++) {
                    const uint32_t* vp = sV + (ks * 8 + tg) * ASTR + nt * 8 + gq;
                    uint32_t bv[2] = { vp[0], vp[4 * ASTR] };
                    mma1688(Oa[nt], pfr[ks], bv);
                }
            }
        }
        __syncthreads();
    }

    float inv0 = 1.0f / l0, inv1 = 1.0f / l1;
    size_t o0 = ((size_t)(b * SD) + qabs0 + gq) * DD + h * DHH + 2 * tg;
    size_t o1 = o0 + (size_t)8 * DD;
    #pragma unroll
    for (int nt = 0; nt < 8; nt++) {
        *(float2*)(g_att + o0 + nt * 8) =
            make_float2(__uint_as_float(f2tf32(Oa[nt][0] * inv0)),
                        __uint_as_float(f2tf32(Oa[nt][1] * inv0)));
        *(float2*)(g_att + o1 + nt * 8) =
            make_float2(__uint_as_float(f2tf32(Oa[nt][2] * inv1)),
                        __uint_as_float(f2tf32(Oa[nt][3] * inv1)));
    }
}

// ---------------- launch --------------------------------------------------
extern "C" void kernel_launch(void* const* d_in, const int* in_sizes, int n_in,
                              void* d_out, int out_size) {
    const int*   tokens = (const int*)  d_in[0];
    const float* emb    = (const float*)d_in[1];
    const float* pos    = (const float*)d_in[2];
    const float* ln1_g  = (const float*)d_in[3];
    const float* ln1_b  = (const float*)d_in[4];
    const float* ln2_g  = (const float*)d_in[5];
    const float* ln2_b  = (const float*)d_in[6];
    const float* ln3_g  = (const float*)d_in[7];
    const float* ln3_b  = (const float*)d_in[8];
    const float* Wq     = (const float*)d_in[9];
    const float* bq     = (const float*)d_in[10];
    const float* Wk     = (const float*)d_in[11];
    const float* bk     = (const float*)d_in[12];
    const float* Wv     = (const float*)d_in[13];
    const float* bv     = (const float*)d_in[14];
    const float* Wo     = (const float*)d_in[15];
    const float* bo     = (const float*)d_in[16];
    const float* W1     = (const float*)d_in[17];
    const float* b1     = (const float*)d_in[18];
    const float* W2     = (const float*)d_in[19];
    const float* b2     = (const float*)d_in[20];
    float* out = (float*)d_out;

    float *xp, *xtp, *qkvp, *attp, *aop, *xnp, *hp;
    float *wqkvp, *bqkvp, *wop, *w1p, *w2p;
    cudaGetSymbolAddress((void**)&xp,    g_x);
    cudaGetSymbolAddress((void**)&xtp,   g_xt);
    cudaGetSymbolAddress((void**)&qkvp,  g_qkv);
    cudaGetSymbolAddress((void**)&attp,  g_att);
    cudaGetSymbolAddress((void**)&aop,   g_ao);
    cudaGetSymbolAddress((void**)&xnp,   g_xn);
    cudaGetSymbolAddress((void**)&hp,    g_h);
    cudaGetSymbolAddress((void**)&wqkvp, g_wqkv);
    cudaGetSymbolAddress((void**)&bqkvp, g_bqkv);
    cudaGetSymbolAddress((void**)&wop,   g_wo);
    cudaGetSymbolAddress((void**)&w1p,   g_w1);
    cudaGetSymbolAddress((void**)&w2p,   g_w2);

    static bool attr_done = false;
    if (!attr_done) {
        cudaFuncSetAttribute(tc_gemm<0>, cudaFuncAttributeMaxDynamicSharedMemorySize, GEMM_SMEM);
        cudaFuncSetAttribute(tc_gemm<1>, cudaFuncAttributeMaxDynamicSharedMemorySize, GEMM_SMEM);
        cudaFuncSetAttribute(tc_gemm<2>, cudaFuncAttributeMaxDynamicSharedMemorySize, GEMM_SMEM);
        cudaFuncSetAttribute(tc_gemm<3>, cudaFuncAttributeMaxDynamicSharedMemorySize, GEMM_SMEM);
        cudaFuncSetAttribute(attn_tc,    cudaFuncAttributeMaxDynamicSharedMemorySize, ATTN_SMEM);
        attr_done = true;
    }

    dim3 tb(32, 8);
    embed_ln_k<<<NR, 256>>>(tokens, emb, pos, ln1_g, ln1_b);
    transpose_qkvo_k<<<dim3(DD / 32, DD / 32, 4), tb>>>(Wq, Wk, Wv, Wo);
    transpose_k<<<dim3(FFD / 32, DD / 32), tb>>>(W1, w1p, DD, FFD);
    transpose_k<<<dim3(DD / 32, FFD / 32), tb>>>(W2, w2p, FFD, DD);
    pack_bias_k<<<QKVD / 256, 256>>>(bq, bk, bv);

    // fused QKV projection (tf32-rounded output)
    tc_gemm<3><<<dim3(QKVD / 128, NR / 128), 256, GEMM_SMEM>>>(xtp, wqkvp, bqkvp, qkvp, DD, QKVD, nullptr);

    attn_tc<<<dim3(SD / 128, BD * HH), 256, ATTN_SMEM>>>();

    tc_gemm<0><<<dim3(DD / 128, NR / 128), 256, GEMM_SMEM>>>(attp, wop, bo, aop, DD, DD, nullptr);
    ln23_k<<<NR, 256>>>(ln2_g, ln2_b, ln3_g, ln3_b);

    tc_gemm<1><<<dim3(FFD / 128, NR / 128), 256, GEMM_SMEM>>>(xnp, w1p, b1, hp, DD, FFD, nullptr);
    tc_gemm<2><<<dim3(DD / 128, NR / 128), 256, GEMM_SMEM>>>(hp, w2p, b2, out, FFD, DD, xp);
}

// round 13
// speedup vs baseline: 1.0104x; 1.0104x over previous
#include <cuda_runtime.h>
#include <cstdint>
#include <math.h>

#define BD   2
#define SD   2048
#define DD   1024
#define HH   16
#define DHH  64
#define FFD  4096
#define NR   (BD*SD)              // 4096 rows
#define QKVD 3072
#define NEGV (-1000000000.0f)

// ---------------- scratch (static device globals; no allocation allowed) ----
__device__ float g_x   [NR*DD];             // fp32 residual stream
__device__ float g_xt  [NR*DD];             // tf32 shadow of LN1 out
__device__ float g_qkv [(size_t)NR*QKVD];   // fused Q|K|V, tf32 bits
__device__ float g_att [NR*DD];             // tf32 bits
__device__ float g_ao  [NR*DD];             // fp32
__device__ float g_xn  [NR*DD];             // tf32 bits (LN3 out)
__device__ float g_h   [(size_t)NR*FFD];    // tf32 bits (gelu out)
__device__ float g_pad [NR];
__device__ float g_wqkv[(size_t)QKVD*DD];   // tf32 bits
__device__ float g_bqkv[QKVD];
__device__ float g_wo  [DD*DD];             // tf32 bits
__device__ float g_w1  [(size_t)DD*FFD];    // tf32 bits
__device__ float g_w2  [(size_t)DD*FFD];    // tf32 bits

// ---------------- tf32 / mma helpers ----------------------------------------
__device__ __forceinline__ float gelu_f(float x) {
    return 0.5f * x * (1.0f + erff(x * 0.70710678118654752f));
}
__device__ __forceinline__ uint32_t f2tf32(float x) {
    uint32_t t;
    asm("cvt.rna.tf32.f32 %0, %1;" : "=r"(t) : "f"(x));
    return t;
}
__device__ __forceinline__ void mma1688(float* c, const uint32_t* a, const uint32_t* b) {
    asm volatile(
        "mma.sync.aligned.m16n8k8.row.col.f32.tf32.tf32.f32 "
        "{%0,%1,%2,%3}, {%4,%5,%6,%7}, {%8,%9}, {%0,%1,%2,%3};"
        : "+f"(c[0]), "+f"(c[1]), "+f"(c[2]), "+f"(c[3])
        : "r"(a[0]), "r"(a[1]), "r"(a[2]), "r"(a[3]), "r"(b[0]), "r"(b[1]));
}
__device__ __forceinline__ uint32_t smem_u32(const void* p) {
    uint32_t a;
    asm("{ .reg .u64 t; cvta.to.shared.u64 t, %1; cvt.u32.u64 %0, t; }"
        : "=r"(a) : "l"(p));
    return a;
}
#define LDSM4(r0, r1, r2, r3, addr) \
    asm volatile("ldmatrix.sync.aligned.m8n8.x4.shared.b16 {%0,%1,%2,%3}, [%4];" \
                 : "=r"(r0), "=r"(r1), "=r"(r2), "=r"(r3) : "r"(addr))

// ---------------- block-wide sum over 256 threads ---------------------------
__device__ __forceinline__ float blockSum(float v, float* sm) {
    int lane = threadIdx.x & 31;
    #pragma unroll
    for (int o = 16; o; o >>= 1) v += __shfl_xor_sync(0xffffffffu, v, o);
    if (lane == 0) sm[threadIdx.x >> 5] = v;
    __syncthreads();
    float t = sm[lane & 7];
    #pragma unroll
    for (int o = 4; o; o >>= 1) t += __shfl_xor_sync(0xffffffffu, t, o);
    __syncthreads();
    return t;
}

// ---------------- K1: embedding + pos + LN1 -> g_x, g_xt ; pad mask ---------
__global__ void embed_ln_k(const int* __restrict__ tok,
                           const float* __restrict__ emb,
                           const float* __restrict__ pos,
                           const float* __restrict__ gam,
                           const float* __restrict__ bet) {
    __shared__ float sm[8];
    int n = blockIdx.x;
    int t = tok[n];
    int s = n & (SD - 1);
    int c0 = threadIdx.x * 4;
    float4 e = *(const float4*)(emb + (size_t)t * DD + c0);
    float4 p = *(const float4*)(pos + (size_t)s * DD + c0);
    float v0 = e.x + p.x, v1 = e.y + p.y, v2 = e.z + p.z, v3 = e.w + p.w;
    float mean = blockSum(v0 + v1 + v2 + v3, sm) * (1.0f / DD);
    float d0 = v0 - mean, d1 = v1 - mean, d2 = v2 - mean, d3 = v3 - mean;
    float var = blockSum(d0*d0 + d1*d1 + d2*d2 + d3*d3, sm) * (1.0f / DD);
    float rs = rsqrtf(var + 1e-5f);
    float4 gg = *(const float4*)(gam + c0);
    float4 bb = *(const float4*)(bet + c0);
    float4 o;
    o.x = d0 * rs * gg.x + bb.x;
    o.y = d1 * rs * gg.y + bb.y;
    o.z = d2 * rs * gg.z + bb.z;
    o.w = d3 * rs * gg.w + bb.w;
    *(float4*)(g_x + (size_t)n * DD + c0) = o;
    uint4 ot = make_uint4(f2tf32(o.x), f2tf32(o.y), f2tf32(o.z), f2tf32(o.w));
    *(uint4*)(g_xt + (size_t)n * DD + c0) = ot;
    if (threadIdx.x == 0) g_pad[n] = (t == 0) ? NEGV : 0.0f;
}

// -------- fused LN2+LN3: g_x += LN2(g_ao); g_xn = tf32(LN3(g_x)) ------------
__global__ void ln23_k(const float* __restrict__ g2, const float* __restrict__ b2v,
                       const float* __restrict__ g3, const float* __restrict__ b3v) {
    __shared__ float sm[8];
    int n = blockIdx.x;
    int c0 = threadIdx.x * 4;
    float4 av = *(const float4*)(g_ao + (size_t)n * DD + c0);
    float mean = blockSum(av.x + av.y + av.z + av.w, sm) * (1.0f / DD);
    float d0 = av.x - mean, d1 = av.y - mean, d2 = av.z - mean, d3 = av.w - mean;
    float var = blockSum(d0*d0 + d1*d1 + d2*d2 + d3*d3, sm) * (1.0f / DD);
    float rs = rsqrtf(var + 1e-5f);
    float4 gg = *(const float4*)(g2 + c0);
    float4 bb = *(const float4*)(b2v + c0);
    float4 x = *(float4*)(g_x + (size_t)n * DD + c0);
    x.x += d0 * rs * gg.x + bb.x;
    x.y += d1 * rs * gg.y + bb.y;
    x.z += d2 * rs * gg.z + bb.z;
    x.w += d3 * rs * gg.w + bb.w;
    *(float4*)(g_x + (size_t)n * DD + c0) = x;
    float mean3 = blockSum(x.x + x.y + x.z + x.w, sm) * (1.0f / DD);
    float e0 = x.x - mean3, e1 = x.y - mean3, e2 = x.z - mean3, e3 = x.w - mean3;
    float var3 = blockSum(e0*e0 + e1*e1 + e2*e2 + e3*e3, sm) * (1.0f / DD);
    float rs3 = rsqrtf(var3 + 1e-5f);
    float4 g3v = *(const float4*)(g3 + c0);
    float4 b3f = *(const float4*)(b3v + c0);
    uint4 o = make_uint4(f2tf32(e0 * rs3 * g3v.x + b3f.x),
                         f2tf32(e1 * rs3 * g3v.y + b3f.y),
                         f2tf32(e2 * rs3 * g3v.z + b3f.z),
                         f2tf32(e3 * rs3 * g3v.w + b3f.w));
    *(uint4*)(g_xn + (size_t)n * DD + c0) = o;
}

// ---- merged QKV+Wo transpose (blockIdx.z selects; all DDxDD) ---------------
__global__ void transpose_qkvo_k(const float* __restrict__ Wq,
                                 const float* __restrict__ Wk,
                                 const float* __restrict__ Wv,
                                 const float* __restrict__ Wo) {
    __shared__ float t[32][33];
    const float* in = (blockIdx.z == 0) ? Wq : (blockIdx.z == 1) ? Wk
                    : (blockIdx.z == 2) ? Wv : Wo;
    float* out = (blockIdx.z < 3) ? (g_wqkv + (size_t)blockIdx.z * DD * DD) : g_wo;
    int bx = blockIdx.x * 32, by = blockIdx.y * 32;
    int x = bx + threadIdx.x;
    #pragma unroll
    for (int i = 0; i < 4; i++)
        t[threadIdx.y + i * 8][threadIdx.x] = in[(size_t)(by + threadIdx.y + i * 8) * DD + x];
    __syncthreads();
    int xo = by + threadIdx.x;
    #pragma unroll
    for (int i = 0; i < 4; i++)
        out[(size_t)(bx + threadIdx.y + i * 8) * DD + xo] =
            __uint_as_float(f2tf32(t[threadIdx.x][threadIdx.y + i * 8]));
}

// ---- merged W1/W2 transpose: z=0: W1[DD,FFD]->[FFD,DD]; z=1: W2[FFD,DD]->[DD,FFD]
__global__ void transpose_w12_k(const float* __restrict__ W1,
                                const float* __restrict__ W2) {
    __shared__ float t[32][33];
    int z = blockIdx.z;
    const float* in = z ? W2 : W1;
    float* out = z ? g_w2 : g_w1;
    int Cc = z ? DD : FFD;          // input columns
    int R  = z ? FFD : DD;          // output columns
    int bxi = z ? blockIdx.y : blockIdx.x;   // z=1 swaps roles so grid fits
    int byi = z ? blockIdx.x : blockIdx.y;
    int bx = bxi * 32, by = byi * 32;
    int x = bx + threadIdx.x;
    #pragma unroll
    for (int i = 0; i < 4; i++)
        t[threadIdx.y + i * 8][threadIdx.x] = in[(size_t)(by + threadIdx.y + i * 8) * Cc + x];
    __syncthreads();
    int xo = by + threadIdx.x;
    #pragma unroll
    for (int i = 0; i < 4; i++)
        out[(size_t)(bx + threadIdx.y + i * 8) * R + xo] =
            __uint_as_float(f2tf32(t[threadIdx.x][threadIdx.y + i * 8]));
}

// ---------------- bias pack: g_bqkv = [bq | bk | bv] ------------------------
__global__ void pack_bias_k(const float* __restrict__ bq,
                            const float* __restrict__ bk,
                            const float* __restrict__ bv) {
    int i = blockIdx.x * 256 + threadIdx.x;
    float v = (i < 1024) ? bq[i] : (i < 2048) ? bk[i - 1024] : bv[i - 2048];
    g_bqkv[i] = v;
}

// ------ mma.sync tf32 GEMM, double-buffered LDG prefetch + ldmatrix ---------
// EPI 0: +bias fp32   EPI 1: gelu -> tf32   EPI 2: +bias+res fp32
// EPI 3: +bias -> tf32
#define SSTR 36
#define SBUF (128 * SSTR)                  // uint32 per operand per stage
#define GEMM_SMEM (2 * 2 * SBUF * 4)       // 73728 bytes

template <int EPI>
__global__ __launch_bounds__(256, 2)
void tc_gemm(const float* __restrict__ A, const float* __restrict__ Bt,
             const float* __restrict__ bias, float* __restrict__ C,
             int K, int Mout, const float* __restrict__ res) {
    extern __shared__ uint32_t dsm[];

    int tid  = threadIdx.x;
    int wid  = tid >> 5;
    int lane = tid & 31;
    int wm   = wid >> 1;
    int wn   = wid & 1;
    int gq   = lane >> 2;
    int tg   = lane & 3;

    int r  = tid >> 1;
    int cb = (tid & 1) * 16;
    const float* ArowP = A  + (size_t)(blockIdx.y * 128 + r) * K + cb;
    const float* BrowP = Bt + (size_t)(blockIdx.x * 128 + r) * K + cb;
    uint32_t rowoff = r * SSTR + cb;
    uint32_t sbase = smem_u32(dsm);

    uint32_t aoffB[2], boffB[4];
    #pragma unroll
    for (int mt = 0; mt < 2; mt++)
        aoffB[mt] = ((wm * 32 + mt * 16 + (lane & 15)) * SSTR + ((lane >> 4) << 2)) * 4;
    #pragma unroll
    for (int p = 0; p < 4; p++)
        boffB[p] = (SBUF + (wn * 64 + p * 16 + ((lane >> 4) << 3) + (lane & 7)) * SSTR
                    + (((lane >> 3) & 1) << 2)) * 4;

    float acc[2][8][4];
    #pragma unroll
    for (int mt = 0; mt < 2; mt++)
        #pragma unroll
        for (int nt = 0; nt < 8; nt++)
            #pragma unroll
            for (int c = 0; c < 4; c++) acc[mt][nt][c] = 0.0f;

    int NC = K >> 5;
    uint4 pa[4], pb[4];
    #pragma unroll
    for (int q = 0; q < 4; q++) {
        pa[q] = *(const uint4*)(ArowP + q * 4);
        pb[q] = *(const uint4*)(BrowP + q * 4);
    }
    {
        uint32_t* dA = dsm + rowoff;
        uint32_t* dB = dA + SBUF;
        #pragma unroll
        for (int q = 0; q < 4; q++) {
            *(uint4*)(dA + q * 4) = pa[q];
            *(uint4*)(dB + q * 4) = pb[q];
        }
    }
    __syncthreads();

    for (int i = 0; i < NC; i++) {
        uint32_t bufbase = sbase + (i & 1) * (2 * SBUF * 4);
        if (i + 1 < NC) {
            #pragma unroll
            for (int q = 0; q < 4; q++) {
                pa[q] = *(const uint4*)(ArowP + (i + 1) * 32 + q * 4);
                pb[q] = *(const uint4*)(BrowP + (i + 1) * 32 + q * 4);
            }
        }
        #pragma unroll
        for (int ks = 0; ks < 4; ks++) {
            uint32_t kb = ks * 32;
            uint32_t af[2][4], bf[8][2];
            LDSM4(af[0][0], af[0][1], af[0][2], af[0][3], bufbase + aoffB[0] + kb);
            LDSM4(af[1][0], af[1][1], af[1][2], af[1][3], bufbase + aoffB[1] + kb);
            LDSM4(bf[0][0], bf[0][1], bf[1][0], bf[1][1], bufbase + boffB[0] + kb);
            LDSM4(bf[2][0], bf[2][1], bf[3][0], bf[3][1], bufbase + boffB[1] + kb);
            LDSM4(bf[4][0], bf[4][1], bf[5][0], bf[5][1], bufbase + boffB[2] + kb);
            LDSM4(bf[6][0], bf[6][1], bf[7][0], bf[7][1], bufbase + boffB[3] + kb);
            #pragma unroll
            for (int mt = 0; mt < 2; mt++)
                #pragma unroll
                for (int nt = 0; nt < 8; nt++)
                    mma1688(acc[mt][nt], af[mt], bf[nt]);
        }
        if (i + 1 < NC) {
            uint32_t* dA = dsm + ((i + 1) & 1) * 2 * SBUF + rowoff;
            uint32_t* dB = dA + SBUF;
            #pragma unroll
            for (int q = 0; q < 4; q++) {
                *(uint4*)(dA + q * 4) = pa[q];
                *(uint4*)(dB + q * 4) = pb[q];
            }
        }
        __syncthreads();
    }

    #pragma unroll
    for (int mt = 0; mt < 2; mt++) {
        #pragma unroll
        for (int nt = 0; nt < 8; nt++) {
            int col = blockIdx.x * 128 + wn * 64 + nt * 8 + 2 * tg;
            float2 bb = *(const float2*)(bias + col);
            #pragma unroll
            for (int h = 0; h < 2; h++) {
                int row = blockIdx.y * 128 + wm * 32 + mt * 16 + gq + h * 8;
                size_t off = (size_t)row * Mout + col;
                float2 o;
                o.x = acc[mt][nt][2 * h + 0] + bb.x;
                o.y = acc[mt][nt][2 * h + 1] + bb.y;
                if (EPI == 1) { o.x = gelu_f(o.x); o.y = gelu_f(o.y); }
                if (EPI == 2) {
                    float2 rr = *(const float2*)(res + off);
                    o.x += rr.x; o.y += rr.y;
                }
                if (EPI == 1 || EPI == 3) {
                    o.x = __uint_as_float(f2tf32(o.x));
                    o.y = __uint_as_float(f2tf32(o.y));
                }
                *(float2*)(C + off) = o;
            }
        }
    }
}

// ---------------- tensor-core flash attention (tf32) ------------------------
// 128 queries/CTA, 8 warps x 16 queries, key tiles 64. 2 CTAs/SM.
#define ASTR 68

__device__ __forceinline__ void quad_permute(uint32_t p0, uint32_t p1, int lane,
                                             uint32_t& a_lo, uint32_t& a_hi) {
    int tg = lane & 3;
    int base = lane & ~3;
    int l1 = base + (tg >> 1);
    int l2 = base + 2 + (tg >> 1);
    uint32_t s0a = __shfl_sync(0xffffffffu, p0, l1);
    uint32_t s1a = __shfl_sync(0xffffffffu, p1, l1);
    uint32_t s0b = __shfl_sync(0xffffffffu, p0, l2);
    uint32_t s1b = __shfl_sync(0xffffffffu, p1, l2);
    a_lo = (tg & 1) ? s1a : s0a;
    a_hi = (tg & 1) ? s1b : s0b;
}

__global__ __launch_bounds__(256, 2)
void attn_tc() {
    __shared__ uint32_t sK[64 * ASTR];
    __shared__ uint32_t sV[64 * ASTR];
    __shared__ float sPad[64];

    int qt = (gridDim.x - 1) - blockIdx.x;  // longest CTAs first
    int bh = blockIdx.y;
    int b = bh >> 4, h = bh & 15;
    int tid = threadIdx.x;
    int w = tid >> 5, lane = tid & 31;
    int gq = lane >> 2, tg = lane & 3;
    int qabs0 = qt * 128 + w * 16;

    // Q fragments (g_qkv already tf32 bits)
    uint32_t qa[8][4];
    const float* Qb = g_qkv + ((size_t)(b * SD) + qabs0) * QKVD + h * DHH;
    #pragma unroll
    for (int ks = 0; ks < 8; ks++) {
        qa[ks][0] = __float_as_uint(Qb[(size_t)gq * QKVD + ks * 8 + tg]);
        qa[ks][1] = __float_as_uint(Qb[(size_t)(gq + 8) * QKVD + ks * 8 + tg]);
        qa[ks][2] = __float_as_uint(Qb[(size_t)gq * QKVD + ks * 8 + tg + 4]);
        qa[ks][3] = __float_as_uint(Qb[(size_t)(gq + 8) * QKVD + ks * 8 + tg + 4]);
    }

    float m0 = -1e30f, m1 = -1e30f, l0 = 0.0f, l1 = 0.0f;
    float Oa[8][4];
    #pragma unroll
    for (int nt = 0; nt < 8; nt++)
        #pragma unroll
        for (int c = 0; c < 4; c++) Oa[nt][c] = 0.0f;

    int lr = tid >> 2;              // 0..63
    int lc = (tid & 3) * 16;        // 0,16,32,48

    int KBMAX = 2 * qt + 1;
    for (int kb = 0; kb <= KBMAX; kb++) {
        size_t gb = ((size_t)(b * SD) + kb * 64 + lr) * QKVD + h * DHH + lc;
        uint32_t* kRow = sK + lr * ASTR + lc;
        uint32_t* vRow = sV + lr * ASTR + lc;
        #pragma unroll
        for (int q = 0; q < 4; q++) {
            *(uint4*)(kRow + q * 4) = *(const uint4*)(g_qkv + gb + 1024 + q * 4);
            *(uint4*)(vRow + q * 4) = *(const uint4*)(g_qkv + gb + 2048 + q * 4);
        }
        if (tid < 64) sPad[tid] = g_pad[(size_t)b * SD + kb * 64 + tid];
        __syncthreads();

        if (kb * 64 <= qabs0 + 15) {            // warp-uniform causal skip
            float sv[8][4];
            #pragma unroll
            for (int nt = 0; nt < 8; nt++)
                #pragma unroll
                for (int c = 0; c < 4; c++) sv[nt][c] = 0.0f;
            #pragma unroll
            for (int ks = 0; ks < 8; ks++) {
                #pragma unroll
                for (int nt = 0; nt < 8; nt++) {
                    const uint32_t* kp = sK + (nt * 8 + gq) * ASTR + ks * 8 + tg;
                    uint32_t bk[2] = { kp[0], kp[4] };
                    mma1688(sv[nt], qa[ks], bk);
                }
            }
            int q0 = qabs0 + gq, q1 = q0 + 8;
            float mx0 = -1e30f, mx1 = -1e30f;
            #pragma unroll
            for (int nt = 0; nt < 8; nt++) {
                int kc = kb * 64 + nt * 8 + 2 * tg;
                float pad0 = sPad[nt * 8 + 2 * tg];
                float pad1 = sPad[nt * 8 + 2 * tg + 1];
                sv[nt][0] = sv[nt][0] * 0.125f + pad0 + ((kc     > q0) ? NEGV : 0.0f);
                sv[nt][1] = sv[nt][1] * 0.125f + pad1 + ((kc + 1 > q0) ? NEGV : 0.0f);
                sv[nt][2] = sv[nt][2] * 0.125f + pad0 + ((kc     > q1) ? NEGV : 0.0f);
                sv[nt][3] = sv[nt][3] * 0.125f + pad1 + ((kc + 1 > q1) ? NEGV : 0.0f);
                mx0 = fmaxf(mx0, fmaxf(sv[nt][0], sv[nt][1]));
                mx1 = fmaxf(mx1, fmaxf(sv[nt][2], sv[nt][3]));
            }
            mx0 = fmaxf(mx0, __shfl_xor_sync(0xffffffffu, mx0, 1));
            mx0 = fmaxf(mx0, __shfl_xor_sync(0xffffffffu, mx0, 2));
            mx1 = fmaxf(mx1, __shfl_xor_sync(0xffffffffu, mx1, 1));
            mx1 = fmaxf(mx1, __shfl_xor_sync(0xffffffffu, mx1, 2));
            float mn0 = fmaxf(m0, mx0), mn1 = fmaxf(m1, mx1);
            float cr0 = __expf(m0 - mn0), cr1 = __expf(m1 - mn1);
            m0 = mn0; m1 = mn1;

            // exp + permute P fragments IN PLACE over sv (saves 32 registers)
            float rs0 = 0.0f, rs1 = 0.0f;
            #pragma unroll
            for (int nt = 0; nt < 8; nt++) {
                float p0 = __expf(sv[nt][0] - mn0);
                float p1 = __expf(sv[nt][1] - mn0);
                float p2 = __expf(sv[nt][2] - mn1);
                float p3 = __expf(sv[nt][3] - mn1);
                rs0 += p0 + p1; rs1 += p2 + p3;
                uint32_t w0, w1c, w2, w3;
                quad_permute(f2tf32(p0), f2tf32(p1), lane, w0, w2);
                quad_permute(f2tf32(p2), f2tf32(p3), lane, w1c, w3);
                sv[nt][0] = __uint_as_float(w0);
                sv[nt][1] = __uint_as_float(w1c);
                sv[nt][2] = __uint_as_float(w2);
                sv[nt][3] = __uint_as_float(w3);
            }
            rs0 += __shfl_xor_sync(0xffffffffu, rs0, 1);
            rs0 += __shfl_xor_sync(0xffffffffu, rs0, 2);
            rs1 += __shfl_xor_sync(0xffffffffu, rs1, 1);
            rs1 += __shfl_xor_sync(0xffffffffu, rs1, 2);
            l0 = l0 * cr0 + rs0;
            l1 = l1 * cr1 + rs1;
            #pragma unroll
            for (int nt = 0; nt < 8; nt++) {
                Oa[nt][0] *= cr0; Oa[nt][1] *= cr0;
                Oa[nt][2] *= cr1; Oa[nt][3] *= cr1;
            }
            #pragma unroll
            for (int ks = 0; ks < 8; ks++) {
                uint32_t pf[4] = { __float_as_uint(sv[ks][0]), __float_as_uint(sv[ks][1]),
                                   __float_as_uint(sv[ks][2]), __float_as_uint(sv[ks][3]) };
                #pragma unroll
                for (int nt = 0; nt < 8; nt++) {
                    const uint32_t* vp = sV + (ks * 8 + tg) * ASTR + nt * 8 + gq;
                    uint32_t bv[2] = { vp[0], vp[4 * ASTR] };
                    mma1688(Oa[nt], pf, bv);
                }
            }
        }
        __syncthreads();
    }

    float inv0 = 1.0f / l0, inv1 = 1.0f / l1;
    size_t o0 = ((size_t)(b * SD) + qabs0 + gq) * DD + h * DHH + 2 * tg;
    size_t o1 = o0 + (size_t)8 * DD;
    #pragma unroll
    for (int nt = 0; nt < 8; nt++) {
        *(float2*)(g_att + o0 + nt * 8) =
            make_float2(__uint_as_float(f2tf32(Oa[nt][0] * inv0)),
                        __uint_as_float(f2tf32(Oa[nt][1] * inv0)));
        *(float2*)(g_att + o1 + nt * 8) =
            make_float2(__uint_as_float(f2tf32(Oa[nt][2] * inv1)),
                        __uint_as_float(f2tf32(Oa[nt][3] * inv1)));
    }
}

// ---------------- launch --------------------------------------------------
extern "C" void kernel_launch(void* const* d_in, const int* in_sizes, int n_in,
                              void* d_out, int out_size) {
    const int*   tokens = (const int*)  d_in[0];
    const float* emb    = (const float*)d_in[1];
    const float* pos    = (const float*)d_in[2];
    const float* ln1_g  = (const float*)d_in[3];
    const float* ln1_b  = (const float*)d_in[4];
    const float* ln2_g  = (const float*)d_in[5];
    const float* ln2_b  = (const float*)d_in[6];
    const float* ln3_g  = (const float*)d_in[7];
    const float* ln3_b  = (const float*)d_in[8];
    const float* Wq     = (const float*)d_in[9];
    const float* bq     = (const float*)d_in[10];
    const float* Wk     = (const float*)d_in[11];
    const float* bk     = (const float*)d_in[12];
    const float* Wv     = (const float*)d_in[13];
    const float* bv     = (const float*)d_in[14];
    const float* Wo     = (const float*)d_in[15];
    const float* bo     = (const float*)d_in[16];
    const float* W1     = (const float*)d_in[17];
    const float* b1     = (const float*)d_in[18];
    const float* W2     = (const float*)d_in[19];
    const float* b2     = (const float*)d_in[20];
    float* out = (float*)d_out;

    float *xp, *xtp, *qkvp, *attp, *aop, *xnp, *hp;
    float *wqkvp, *bqkvp, *wop, *w1p, *w2p;
    cudaGetSymbolAddress((void**)&xp,    g_x);
    cudaGetSymbolAddress((void**)&xtp,   g_xt);
    cudaGetSymbolAddress((void**)&qkvp,  g_qkv);
    cudaGetSymbolAddress((void**)&attp,  g_att);
    cudaGetSymbolAddress((void**)&aop,   g_ao);
    cudaGetSymbolAddress((void**)&xnp,   g_xn);
    cudaGetSymbolAddress((void**)&hp,    g_h);
    cudaGetSymbolAddress((void**)&wqkvp, g_wqkv);
    cudaGetSymbolAddress((void**)&bqkvp, g_bqkv);
    cudaGetSymbolAddress((void**)&wop,   g_wo);
    cudaGetSymbolAddress((void**)&w1p,   g_w1);
    cudaGetSymbolAddress((void**)&w2p,   g_w2);

    static bool attr_done = false;
    if (!attr_done) {
        cudaFuncSetAttribute(tc_gemm<0>, cudaFuncAttributeMaxDynamicSharedMemorySize, GEMM_SMEM);
        cudaFuncSetAttribute(tc_gemm<1>, cudaFuncAttributeMaxDynamicSharedMemorySize, GEMM_SMEM);
        cudaFuncSetAttribute(tc_gemm<2>, cudaFuncAttributeMaxDynamicSharedMemorySize, GEMM_SMEM);
        cudaFuncSetAttribute(tc_gemm<3>, cudaFuncAttributeMaxDynamicSharedMemorySize, GEMM_SMEM);
        attr_done = true;
    }

    dim3 tb(32, 8);
    embed_ln_k<<<NR, 256>>>(tokens, emb, pos, ln1_g, ln1_b);
    transpose_qkvo_k<<<dim3(DD / 32, DD / 32, 4), tb>>>(Wq, Wk, Wv, Wo);
    transpose_w12_k<<<dim3(FFD / 32, DD / 32, 2), tb>>>(W1, W2);
    pack_bias_k<<<QKVD / 256, 256>>>(bq, bk, bv);

    // fused QKV projection (tf32-rounded output)
    tc_gemm<3><<<dim3(QKVD / 128, NR / 128), 256, GEMM_SMEM>>>(xtp, wqkvp, bqkvp, qkvp, DD, QKVD, nullptr);

    attn_tc<<<dim3(SD / 128, BD * HH), 256>>>();

    tc_gemm<0><<<dim3(DD / 128, NR / 128), 256, GEMM_SMEM>>>(attp, wop, bo, aop, DD, DD, nullptr);
    ln23_k<<<NR, 256>>>(ln2_g, ln2_b, ln3_g, ln3_b);

    tc_gemm<1><<<dim3(FFD / 128, NR / 128), 256, GEMM_SMEM>>>(xnp, w1p, b1, hp, DD, FFD, nullptr);
    tc_gemm<2><<<dim3(DD / 128, NR / 128), 256, GEMM_SMEM>>>(hp, w2p, b2, out, FFD, DD, xp);
}

// round 14
// speedup vs baseline: 1.0196x; 1.0091x over previous
#include <cuda_runtime.h>
#include <cstdint>
#include <math.h>

#define BD   2
#define SD   2048
#define DD   1024
#define HH   16
#define DHH  64
#define FFD  4096
#define NR   (BD*SD)              // 4096 rows
#define QKVD 3072
#define NEGV (-1000000000.0f)

// ---------------- scratch (static device globals; no allocation allowed) ----
__device__ float g_x   [NR*DD];             // fp32 residual stream
__device__ float g_xt  [NR*DD];             // tf32 shadow of LN1 out
__device__ float g_qkv [(size_t)NR*QKVD];   // fused Q|K|V, tf32 bits
__device__ float g_att [NR*DD];             // tf32 bits
__device__ float g_ao  [NR*DD];             // fp32
__device__ float g_xn  [NR*DD];             // tf32 bits (LN3 out)
__device__ float g_h   [(size_t)NR*FFD];    // tf32 bits (gelu out)
__device__ float g_pad [NR];
__device__ float g_wqkv[(size_t)QKVD*DD];   // tf32 bits
__device__ float g_bqkv[QKVD];
__device__ float g_wo  [DD*DD];             // tf32 bits
__device__ float g_w1  [(size_t)DD*FFD];    // tf32 bits
__device__ float g_w2  [(size_t)DD*FFD];    // tf32 bits

// ---------------- tf32 / mma helpers ----------------------------------------
__device__ __forceinline__ float gelu_f(float x) {
    return 0.5f * x * (1.0f + erff(x * 0.70710678118654752f));
}
__device__ __forceinline__ uint32_t f2tf32(float x) {
    uint32_t t;
    asm("cvt.rna.tf32.f32 %0, %1;" : "=r"(t) : "f"(x));
    return t;
}
__device__ __forceinline__ void mma1688(float* c, const uint32_t* a, const uint32_t* b) {
    asm volatile(
        "mma.sync.aligned.m16n8k8.row.col.f32.tf32.tf32.f32 "
        "{%0,%1,%2,%3}, {%4,%5,%6,%7}, {%8,%9}, {%0,%1,%2,%3};"
        : "+f"(c[0]), "+f"(c[1]), "+f"(c[2]), "+f"(c[3])
        : "r"(a[0]), "r"(a[1]), "r"(a[2]), "r"(a[3]), "r"(b[0]), "r"(b[1]));
}
__device__ __forceinline__ uint32_t smem_u32(const void* p) {
    uint32_t a;
    asm("{ .reg .u64 t; cvta.to.shared.u64 t, %1; cvt.u32.u64 %0, t; }"
        : "=r"(a) : "l"(p));
    return a;
}
#define LDSM4(r0, r1, r2, r3, addr) \
    asm volatile("ldmatrix.sync.aligned.m8n8.x4.shared.b16 {%0,%1,%2,%3}, [%4];" \
                 : "=r"(r0), "=r"(r1), "=r"(r2), "=r"(r3) : "r"(addr))

__device__ __forceinline__ float warpSum(float v) {
    #pragma unroll
    for (int o = 16; o; o >>= 1) v += __shfl_xor_sync(0xffffffffu, v, o);
    return v;
}

// ------- K1: embedding + pos + LN1 -> g_x, g_xt ; pad mask (warp/row) -------
__global__ void embed_ln_k(const int* __restrict__ tok,
                           const float* __restrict__ emb,
                           const float* __restrict__ pos,
                           const float* __restrict__ gam,
                           const float* __restrict__ bet) {
    int w = threadIdx.x >> 5, lane = threadIdx.x & 31;
    int n = blockIdx.x * 8 + w;
    int t = tok[n];
    int s = n & (SD - 1);
    float4 v[8];
    float sum = 0.0f;
    #pragma unroll
    for (int q = 0; q < 8; q++) {
        int c = (q * 32 + lane) * 4;
        float4 e = *(const float4*)(emb + (size_t)t * DD + c);
        float4 p = *(const float4*)(pos + (size_t)s * DD + c);
        v[q].x = e.x + p.x; v[q].y = e.y + p.y;
        v[q].z = e.z + p.z; v[q].w = e.w + p.w;
        sum += v[q].x + v[q].y + v[q].z + v[q].w;
    }
    float mean = warpSum(sum) * (1.0f / DD);
    float vs = 0.0f;
    #pragma unroll
    for (int q = 0; q < 8; q++) {
        float d0 = v[q].x - mean, d1 = v[q].y - mean;
        float d2 = v[q].z - mean, d3 = v[q].w - mean;
        vs += d0*d0 + d1*d1 + d2*d2 + d3*d3;
    }
    float rs = rsqrtf(warpSum(vs) * (1.0f / DD) + 1e-5f);
    #pragma unroll
    for (int q = 0; q < 8; q++) {
        int c = (q * 32 + lane) * 4;
        float4 gg = *(const float4*)(gam + c);
        float4 bb = *(const float4*)(bet + c);
        float4 o;
        o.x = (v[q].x - mean) * rs * gg.x + bb.x;
        o.y = (v[q].y - mean) * rs * gg.y + bb.y;
        o.z = (v[q].z - mean) * rs * gg.z + bb.z;
        o.w = (v[q].w - mean) * rs * gg.w + bb.w;
        *(float4*)(g_x + (size_t)n * DD + c) = o;
        uint4 ot = make_uint4(f2tf32(o.x), f2tf32(o.y), f2tf32(o.z), f2tf32(o.w));
        *(uint4*)(g_xt + (size_t)n * DD + c) = ot;
    }
    if (lane == 0) g_pad[n] = (t == 0) ? NEGV : 0.0f;
}

// -- fused LN2+LN3 (warp/row): g_x += LN2(g_ao); g_xn = tf32(LN3(g_x)) -------
__global__ void ln23_k(const float* __restrict__ g2, const float* __restrict__ b2v,
                       const float* __restrict__ g3, const float* __restrict__ b3v) {
    int w = threadIdx.x >> 5, lane = threadIdx.x & 31;
    int n = blockIdx.x * 8 + w;
    float4 a[8], x[8];
    float sum = 0.0f;
    #pragma unroll
    for (int q = 0; q < 8; q++) {
        int c = (q * 32 + lane) * 4;
        a[q] = *(const float4*)(g_ao + (size_t)n * DD + c);
        sum += a[q].x + a[q].y + a[q].z + a[q].w;
    }
    float mean = warpSum(sum) * (1.0f / DD);
    float vs = 0.0f;
    #pragma unroll
    for (int q = 0; q < 8; q++) {
        float d0 = a[q].x - mean, d1 = a[q].y - mean;
        float d2 = a[q].z - mean, d3 = a[q].w - mean;
        vs += d0*d0 + d1*d1 + d2*d2 + d3*d3;
    }
    float rs = rsqrtf(warpSum(vs) * (1.0f / DD) + 1e-5f);
    float sum3 = 0.0f;
    #pragma unroll
    for (int q = 0; q < 8; q++) {
        int c = (q * 32 + lane) * 4;
        float4 gg = *(const float4*)(g2 + c);
        float4 bb = *(const float4*)(b2v + c);
        x[q] = *(const float4*)(g_x + (size_t)n * DD + c);
        x[q].x += (a[q].x - mean) * rs * gg.x + bb.x;
        x[q].y += (a[q].y - mean) * rs * gg.y + bb.y;
        x[q].z += (a[q].z - mean) * rs * gg.z + bb.z;
        x[q].w += (a[q].w - mean) * rs * gg.w + bb.w;
        *(float4*)(g_x + (size_t)n * DD + c) = x[q];
        sum3 += x[q].x + x[q].y + x[q].z + x[q].w;
    }
    float mean3 = warpSum(sum3) * (1.0f / DD);
    float vs3 = 0.0f;
    #pragma unroll
    for (int q = 0; q < 8; q++) {
        float d0 = x[q].x - mean3, d1 = x[q].y - mean3;
        float d2 = x[q].z - mean3, d3 = x[q].w - mean3;
        vs3 += d0*d0 + d1*d1 + d2*d2 + d3*d3;
    }
    float rs3 = rsqrtf(warpSum(vs3) * (1.0f / DD) + 1e-5f);
    #pragma unroll
    for (int q = 0; q < 8; q++) {
        int c = (q * 32 + lane) * 4;
        float4 gg = *(const float4*)(g3 + c);
        float4 bb = *(const float4*)(b3v + c);
        uint4 o = make_uint4(f2tf32((x[q].x - mean3) * rs3 * gg.x + bb.x),
                             f2tf32((x[q].y - mean3) * rs3 * gg.y + bb.y),
                             f2tf32((x[q].z - mean3) * rs3 * gg.z + bb.z),
                             f2tf32((x[q].w - mean3) * rs3 * gg.w + bb.w));
        *(uint4*)(g_xn + (size_t)n * DD + c) = o;
    }
}

// ---- merged QKV+Wo transpose (blockIdx.z selects; all DDxDD) ---------------
__global__ void transpose_qkvo_k(const float* __restrict__ Wq,
                                 const float* __restrict__ Wk,
                                 const float* __restrict__ Wv,
                                 const float* __restrict__ Wo) {
    __shared__ float t[32][33];
    const float* in = (blockIdx.z == 0) ? Wq : (blockIdx.z == 1) ? Wk
                    : (blockIdx.z == 2) ? Wv : Wo;
    float* out = (blockIdx.z < 3) ? (g_wqkv + (size_t)blockIdx.z * DD * DD) : g_wo;
    int bx = blockIdx.x * 32, by = blockIdx.y * 32;
    int x = bx + threadIdx.x;
    #pragma unroll
    for (int i = 0; i < 4; i++)
        t[threadIdx.y + i * 8][threadIdx.x] = in[(size_t)(by + threadIdx.y + i * 8) * DD + x];
    __syncthreads();
    int xo = by + threadIdx.x;
    #pragma unroll
    for (int i = 0; i < 4; i++)
        out[(size_t)(bx + threadIdx.y + i * 8) * DD + xo] =
            __uint_as_float(f2tf32(t[threadIdx.x][threadIdx.y + i * 8]));
}

// ---- merged W1/W2 transpose ------------------------------------------------
__global__ void transpose_w12_k(const float* __restrict__ W1,
                                const float* __restrict__ W2) {
    __shared__ float t[32][33];
    int z = blockIdx.z;
    const float* in = z ? W2 : W1;
    float* out = z ? g_w2 : g_w1;
    int Cc = z ? DD : FFD;
    int R  = z ? FFD : DD;
    int bxi = z ? blockIdx.y : blockIdx.x;
    int byi = z ? blockIdx.x : blockIdx.y;
    int bx = bxi * 32, by = byi * 32;
    int x = bx + threadIdx.x;
    #pragma unroll
    for (int i = 0; i < 4; i++)
        t[threadIdx.y + i * 8][threadIdx.x] = in[(size_t)(by + threadIdx.y + i * 8) * Cc + x];
    __syncthreads();
    int xo = by + threadIdx.x;
    #pragma unroll
    for (int i = 0; i < 4; i++)
        out[(size_t)(bx + threadIdx.y + i * 8) * R + xo] =
            __uint_as_float(f2tf32(t[threadIdx.x][threadIdx.y + i * 8]));
}

// ---------------- bias pack: g_bqkv = [bq | bk | bv] ------------------------
__global__ void pack_bias_k(const float* __restrict__ bq,
                            const float* __restrict__ bk,
                            const float* __restrict__ bv) {
    int i = blockIdx.x * 256 + threadIdx.x;
    float v = (i < 1024) ? bq[i] : (i < 2048) ? bk[i - 1024] : bv[i - 2048];
    g_bqkv[i] = v;
}

// ------ mma.sync tf32 GEMM, double-buffered LDG prefetch + ldmatrix ---------
#define SSTR 36
#define SBUF (128 * SSTR)
#define GEMM_SMEM (2 * 2 * SBUF * 4)       // 73728 bytes

template <int EPI>
__global__ __launch_bounds__(256, 2)
void tc_gemm(const float* __restrict__ A, const float* __restrict__ Bt,
             const float* __restrict__ bias, float* __restrict__ C,
             int K, int Mout, const float* __restrict__ res) {
    extern __shared__ uint32_t dsm[];

    int tid  = threadIdx.x;
    int wid  = tid >> 5;
    int lane = tid & 31;
    int wm   = wid >> 1;
    int wn   = wid & 1;
    int gq   = lane >> 2;
    int tg   = lane & 3;

    int r  = tid >> 1;
    int cb = (tid & 1) * 16;
    const float* ArowP = A  + (size_t)(blockIdx.y * 128 + r) * K + cb;
    const float* BrowP = Bt + (size_t)(blockIdx.x * 128 + r) * K + cb;
    uint32_t rowoff = r * SSTR + cb;
    uint32_t sbase = smem_u32(dsm);

    uint32_t aoffB[2], boffB[4];
    #pragma unroll
    for (int mt = 0; mt < 2; mt++)
        aoffB[mt] = ((wm * 32 + mt * 16 + (lane & 15)) * SSTR + ((lane >> 4) << 2)) * 4;
    #pragma unroll
    for (int p = 0; p < 4; p++)
        boffB[p] = (SBUF + (wn * 64 + p * 16 + ((lane >> 4) << 3) + (lane & 7)) * SSTR
                    + (((lane >> 3) & 1) << 2)) * 4;

    float acc[2][8][4];
    #pragma unroll
    for (int mt = 0; mt < 2; mt++)
        #pragma unroll
        for (int nt = 0; nt < 8; nt++)
            #pragma unroll
            for (int c = 0; c < 4; c++) acc[mt][nt][c] = 0.0f;

    int NC = K >> 5;
    uint4 pa[4], pb[4];
    #pragma unroll
    for (int q = 0; q < 4; q++) {
        pa[q] = *(const uint4*)(ArowP + q * 4);
        pb[q] = *(const uint4*)(BrowP + q * 4);
    }
    {
        uint32_t* dA = dsm + rowoff;
        uint32_t* dB = dA + SBUF;
        #pragma unroll
        for (int q = 0; q < 4; q++) {
            *(uint4*)(dA + q * 4) = pa[q];
            *(uint4*)(dB + q * 4) = pb[q];
        }
    }
    __syncthreads();

    for (int i = 0; i < NC; i++) {
        uint32_t bufbase = sbase + (i & 1) * (2 * SBUF * 4);
        if (i + 1 < NC) {
            #pragma unroll
            for (int q = 0; q < 4; q++) {
                pa[q] = *(const uint4*)(ArowP + (i + 1) * 32 + q * 4);
                pb[q] = *(const uint4*)(BrowP + (i + 1) * 32 + q * 4);
            }
        }
        #pragma unroll
        for (int ks = 0; ks < 4; ks++) {
            uint32_t kb = ks * 32;
            uint32_t af[2][4], bf[8][2];
            LDSM4(af[0][0], af[0][1], af[0][2], af[0][3], bufbase + aoffB[0] + kb);
            LDSM4(af[1][0], af[1][1], af[1][2], af[1][3], bufbase + aoffB[1] + kb);
            LDSM4(bf[0][0], bf[0][1], bf[1][0], bf[1][1], bufbase + boffB[0] + kb);
            LDSM4(bf[2][0], bf[2][1], bf[3][0], bf[3][1], bufbase + boffB[1] + kb);
            LDSM4(bf[4][0], bf[4][1], bf[5][0], bf[5][1], bufbase + boffB[2] + kb);
            LDSM4(bf[6][0], bf[6][1], bf[7][0], bf[7][1], bufbase + boffB[3] + kb);
            #pragma unroll
            for (int mt = 0; mt < 2; mt++)
                #pragma unroll
                for (int nt = 0; nt < 8; nt++)
                    mma1688(acc[mt][nt], af[mt], bf[nt]);
        }
        if (i + 1 < NC) {
            uint32_t* dA = dsm + ((i + 1) & 1) * 2 * SBUF + rowoff;
            uint32_t* dB = dA + SBUF;
            #pragma unroll
            for (int q = 0; q < 4; q++) {
                *(uint4*)(dA + q * 4) = pa[q];
                *(uint4*)(dB + q * 4) = pb[q];
            }
        }
        __syncthreads();
    }

    #pragma unroll
    for (int mt = 0; mt < 2; mt++) {
        #pragma unroll
        for (int nt = 0; nt < 8; nt++) {
            int col = blockIdx.x * 128 + wn * 64 + nt * 8 + 2 * tg;
            float2 bb = *(const float2*)(bias + col);
            #pragma unroll
            for (int h = 0; h < 2; h++) {
                int row = blockIdx.y * 128 + wm * 32 + mt * 16 + gq + h * 8;
                size_t off = (size_t)row * Mout + col;
                float2 o;
                o.x = acc[mt][nt][2 * h + 0] + bb.x;
                o.y = acc[mt][nt][2 * h + 1] + bb.y;
                if (EPI == 1) { o.x = gelu_f(o.x); o.y = gelu_f(o.y); }
                if (EPI == 2) {
                    float2 rr = *(const float2*)(res + off);
                    o.x += rr.x; o.y += rr.y;
                }
                if (EPI == 1 || EPI == 3) {
                    o.x = __uint_as_float(f2tf32(o.x));
                    o.y = __uint_as_float(f2tf32(o.y));
                }
                *(float2*)(C + off) = o;
            }
        }
    }
}

// ---------------- tensor-core flash attention (tf32) ------------------------
// 128 queries/CTA, 8 warps x 16 queries, key tiles 64. 2 CTAs/SM.
#define ASTR 68

__device__ __forceinline__ void quad_permute(uint32_t p0, uint32_t p1, int lane,
                                             uint32_t& a_lo, uint32_t& a_hi) {
    int tg = lane & 3;
    int base = lane & ~3;
    int l1 = base + (tg >> 1);
    int l2 = base + 2 + (tg >> 1);
    uint32_t s0a = __shfl_sync(0xffffffffu, p0, l1);
    uint32_t s1a = __shfl_sync(0xffffffffu, p1, l1);
    uint32_t s0b = __shfl_sync(0xffffffffu, p0, l2);
    uint32_t s1b = __shfl_sync(0xffffffffu, p1, l2);
    a_lo = (tg & 1) ? s1a : s0a;
    a_hi = (tg & 1) ? s1b : s0b;
}

__global__ __launch_bounds__(256, 2)
void attn_tc() {
    __shared__ uint32_t sK[64 * ASTR];
    __shared__ uint32_t sV[64 * ASTR];
    __shared__ float sPad[64];

    int qt = (gridDim.x - 1) - blockIdx.x;  // longest CTAs first
    int bh = blockIdx.y;
    int b = bh >> 4, h = bh & 15;
    int tid = threadIdx.x;
    int lane = tid & 31;
    int w = tid >> 5;
    int gq = lane >> 2, tg = lane & 3;
    int qabs0 = qt * 128 + w * 16;

    // ldmatrix byte-offsets for K fragments (GEMM boffB pattern, no wn)
    uint32_t koffB[4];
    #pragma unroll
    for (int p = 0; p < 4; p++)
        koffB[p] = ((p * 16 + ((lane >> 4) << 3) + (lane & 7)) * ASTR
                    + (((lane >> 3) & 1) << 2)) * 4;
    uint32_t skb = smem_u32(sK);

    // Q fragments (g_qkv already tf32 bits)
    uint32_t qa[8][4];
    const float* Qb = g_qkv + ((size_t)(b * SD) + qabs0) * QKVD + h * DHH;
    #pragma unroll
    for (int ks = 0; ks < 8; ks++) {
        qa[ks][0] = __float_as_uint(Qb[(size_t)gq * QKVD + ks * 8 + tg]);
        qa[ks][1] = __float_as_uint(Qb[(size_t)(gq + 8) * QKVD + ks * 8 + tg]);
        qa[ks][2] = __float_as_uint(Qb[(size_t)gq * QKVD + ks * 8 + tg + 4]);
        qa[ks][3] = __float_as_uint(Qb[(size_t)(gq + 8) * QKVD + ks * 8 + tg + 4]);
    }

    float m0 = -1e30f, m1 = -1e30f, l0 = 0.0f, l1 = 0.0f;
    float Oa[8][4];
    #pragma unroll
    for (int nt = 0; nt < 8; nt++)
        #pragma unroll
        for (int c = 0; c < 4; c++) Oa[nt][c] = 0.0f;

    int lr = tid >> 2;              // 0..63
    int lc = (tid & 3) * 16;        // 0,16,32,48

    int KBMAX = 2 * qt + 1;
    for (int kb = 0; kb <= KBMAX; kb++) {
        size_t gb = ((size_t)(b * SD) + kb * 64 + lr) * QKVD + h * DHH + lc;
        uint32_t* kRow = sK + lr * ASTR + lc;
        uint32_t* vRow = sV + lr * ASTR + lc;
        #pragma unroll
        for (int q = 0; q < 4; q++) {
            *(uint4*)(kRow + q * 4) = *(const uint4*)(g_qkv + gb + 1024 + q * 4);
            *(uint4*)(vRow + q * 4) = *(const uint4*)(g_qkv + gb + 2048 + q * 4);
        }
        if (tid < 64) sPad[tid] = g_pad[(size_t)b * SD + kb * 64 + tid];
        __syncthreads();

        if (kb * 64 <= qabs0 + 15) {            // warp-uniform causal skip
            float sv[8][4];
            #pragma unroll
            for (int nt = 0; nt < 8; nt++)
                #pragma unroll
                for (int c = 0; c < 4; c++) sv[nt][c] = 0.0f;
            #pragma unroll
            for (int ks = 0; ks < 8; ks++) {
                uint32_t kf[8][2];
                uint32_t kbo = ks * 32;
                LDSM4(kf[0][0], kf[0][1], kf[1][0], kf[1][1], skb + koffB[0] + kbo);
                LDSM4(kf[2][0], kf[2][1], kf[3][0], kf[3][1], skb + koffB[1] + kbo);
                LDSM4(kf[4][0], kf[4][1], kf[5][0], kf[5][1], skb + koffB[2] + kbo);
                LDSM4(kf[6][0], kf[6][1], kf[7][0], kf[7][1], skb + koffB[3] + kbo);
                #pragma unroll
                for (int nt = 0; nt < 8; nt++)
                    mma1688(sv[nt], qa[ks], kf[nt]);
            }
            int q0 = qabs0 + gq, q1 = q0 + 8;
            float mx0 = -1e30f, mx1 = -1e30f;
            #pragma unroll
            for (int nt = 0; nt < 8; nt++) {
                int kc = kb * 64 + nt * 8 + 2 * tg;
                float pad0 = sPad[nt * 8 + 2 * tg];
                float pad1 = sPad[nt * 8 + 2 * tg + 1];
                sv[nt][0] = sv[nt][0] * 0.125f + pad0 + ((kc     > q0) ? NEGV : 0.0f);
                sv[nt][1] = sv[nt][1] * 0.125f + pad1 + ((kc + 1 > q0) ? NEGV : 0.0f);
                sv[nt][2] = sv[nt][2] * 0.125f + pad0 + ((kc     > q1) ? NEGV : 0.0f);
                sv[nt][3] = sv[nt][3] * 0.125f + pad1 + ((kc + 1 > q1) ? NEGV : 0.0f);
                mx0 = fmaxf(mx0, fmaxf(sv[nt][0], sv[nt][1]));
                mx1 = fmaxf(mx1, fmaxf(sv[nt][2], sv[nt][3]));
            }
            mx0 = fmaxf(mx0, __shfl_xor_sync(0xffffffffu, mx0, 1));
            mx0 = fmaxf(mx0, __shfl_xor_sync(0xffffffffu, mx0, 2));
            mx1 = fmaxf(mx1, __shfl_xor_sync(0xffffffffu, mx1, 1));
            mx1 = fmaxf(mx1, __shfl_xor_sync(0xffffffffu, mx1, 2));
            float mn0 = fmaxf(m0, mx0), mn1 = fmaxf(m1, mx1);
            float cr0 = __expf(m0 - mn0), cr1 = __expf(m1 - mn1);
            m0 = mn0; m1 = mn1;

            float rs0 = 0.0f, rs1 = 0.0f;
            #pragma unroll
            for (int nt = 0; nt < 8; nt++) {
                float p0 = __expf(sv[nt][0] - mn0);
                float p1 = __expf(sv[nt][1] - mn0);
                float p2 = __expf(sv[nt][2] - mn1);
                float p3 = __expf(sv[nt][3] - mn1);
                rs0 += p0 + p1; rs1 += p2 + p3;
                uint32_t w0, w1c, w2, w3;
                quad_permute(f2tf32(p0), f2tf32(p1), lane, w0, w2);
                quad_permute(f2tf32(p2), f2tf32(p3), lane, w1c, w3);
                sv[nt][0] = __uint_as_float(w0);
                sv[nt][1] = __uint_as_float(w1c);
                sv[nt][2] = __uint_as_float(w2);
                sv[nt][3] = __uint_as_float(w3);
            }
            rs0 += __shfl_xor_sync(0xffffffffu, rs0, 1);
            rs0 += __shfl_xor_sync(0xffffffffu, rs0, 2);
            rs1 += __shfl_xor_sync(0xffffffffu, rs1, 1);
            rs1 += __shfl_xor_sync(0xffffffffu, rs1, 2);
            l0 = l0 * cr0 + rs0;
            l1 = l1 * cr1 + rs1;
            #pragma unroll
            for (int nt = 0; nt < 8; nt++) {
                Oa[nt][0] *= cr0; Oa[nt][1] *= cr0;
                Oa[nt][2] *= cr1; Oa[nt][3] *= cr1;
            }
            #pragma unroll
            for (int ks = 0; ks < 8; ks++) {
                uint32_t pf[4] = { __float_as_uint(sv[ks][0]), __float_as_uint(sv[ks][1]),
                                   __float_as_uint(sv[ks][2]), __float_as_uint(sv[ks][3]) };
                #pragma unroll
                for (int nt = 0; nt < 8; nt++) {
                    const uint32_t* vp = sV + (ks * 8 + tg) * ASTR + nt * 8 + gq;
                    uint32_t bv[2] = { vp[0], vp[4 * ASTR] };
                    mma1688(Oa[nt], pf, bv);
                }
            }
        }
        __syncthreads();
    }

    float inv0 = 1.0f / l0, inv1 = 1.0f / l1;
    size_t o0 = ((size_t)(b * SD) + qabs0 + gq) * DD + h * DHH + 2 * tg;
    size_t o1 = o0 + (size_t)8 * DD;
    #pragma unroll
    for (int nt = 0; nt < 8; nt++) {
        *(float2*)(g_att + o0 + nt * 8) =
            make_float2(__uint_as_float(f2tf32(Oa[nt][0] * inv0)),
                        __uint_as_float(f2tf32(Oa[nt][1] * inv0)));
        *(float2*)(g_att + o1 + nt * 8) =
            make_float2(__uint_as_float(f2tf32(Oa[nt][2] * inv1)),
                        __uint_as_float(f2tf32(Oa[nt][3] * inv1)));
    }
}

// ---------------- launch --------------------------------------------------
extern "C" void kernel_launch(void* const* d_in, const int* in_sizes, int n_in,
                              void* d_out, int out_size) {
    const int*   tokens = (const int*)  d_in[0];
    const float* emb    = (const float*)d_in[1];
    const float* pos    = (const float*)d_in[2];
    const float* ln1_g  = (const float*)d_in[3];
    const float* ln1_b  = (const float*)d_in[4];
    const float* ln2_g  = (const float*)d_in[5];
    const float* ln2_b  = (const float*)d_in[6];
    const float* ln3_g  = (const float*)d_in[7];
    const float* ln3_b  = (const float*)d_in[8];
    const float* Wq     = (const float*)d_in[9];
    const float* bq     = (const float*)d_in[10];
    const float* Wk     = (const float*)d_in[11];
    const float* bk     = (const float*)d_in[12];
    const float* Wv     = (const float*)d_in[13];
    const float* bv     = (const float*)d_in[14];
    const float* Wo     = (const float*)d_in[15];
    const float* bo     = (const float*)d_in[16];
    const float* W1     = (const float*)d_in[17];
    const float* b1     = (const float*)d_in[18];
    const float* W2     = (const float*)d_in[19];
    const float* b2     = (const float*)d_in[20];
    float* out = (float*)d_out;

    float *xp, *xtp, *qkvp, *attp, *aop, *xnp, *hp;
    float *wqkvp, *bqkvp, *wop, *w1p, *w2p;
    cudaGetSymbolAddress((void**)&xp,    g_x);
    cudaGetSymbolAddress((void**)&xtp,   g_xt);
    cudaGetSymbolAddress((void**)&qkvp,  g_qkv);
    cudaGetSymbolAddress((void**)&attp,  g_att);
    cudaGetSymbolAddress((void**)&aop,   g_ao);
    cudaGetSymbolAddress((void**)&xnp,   g_xn);
    cudaGetSymbolAddress((void**)&hp,    g_h);
    cudaGetSymbolAddress((void**)&wqkvp, g_wqkv);
    cudaGetSymbolAddress((void**)&bqkvp, g_bqkv);
    cudaGetSymbolAddress((void**)&wop,   g_wo);
    cudaGetSymbolAddress((void**)&w1p,   g_w1);
    cudaGetSymbolAddress((void**)&w2p,   g_w2);

    static bool attr_done = false;
    if (!attr_done) {
        cudaFuncSetAttribute(tc_gemm<0>, cudaFuncAttributeMaxDynamicSharedMemorySize, GEMM_SMEM);
        cudaFuncSetAttribute(tc_gemm<1>, cudaFuncAttributeMaxDynamicSharedMemorySize, GEMM_SMEM);
        cudaFuncSetAttribute(tc_gemm<2>, cudaFuncAttributeMaxDynamicSharedMemorySize, GEMM_SMEM);
        cudaFuncSetAttribute(tc_gemm<3>, cudaFuncAttributeMaxDynamicSharedMemorySize, GEMM_SMEM);
        attr_done = true;
    }

    dim3 tb(32, 8);
    embed_ln_k<<<NR / 8, 256>>>(tokens, emb, pos, ln1_g, ln1_b);
    transpose_qkvo_k<<<dim3(DD / 32, DD / 32, 4), tb>>>(Wq, Wk, Wv, Wo);
    transpose_w12_k<<<dim3(FFD / 32, DD / 32, 2), tb>>>(W1, W2);
    pack_bias_k<<<QKVD / 256, 256>>>(bq, bk, bv);

    // fused QKV projection (tf32-rounded output)
    tc_gemm<3><<<dim3(QKVD / 128, NR / 128), 256, GEMM_SMEM>>>(xtp, wqkvp, bqkvp, qkvp, DD, QKVD, nullptr);

    attn_tc<<<dim3(SD / 128, BD * HH), 256>>>();

    tc_gemm<0><<<dim3(DD / 128, NR / 128), 256, GEMM_SMEM>>>(attp, wop, bo, aop, DD, DD, nullptr);
    ln23_k<<<NR / 8, 256>>>(ln2_g, ln2_b, ln3_g, ln3_b);

    tc_gemm<1><<<dim3(FFD / 128, NR / 128), 256, GEMM_SMEM>>>(xnp, w1p, b1, hp, DD, FFD, nullptr);
    tc_gemm<2><<<dim3(DD / 128, NR / 128), 256, GEMM_SMEM>>>(hp, w2p, b2, out, FFD, DD, xp);
}

// round 15
// speedup vs baseline: 1.0542x; 1.0339x over previous
#include <cuda_runtime.h>
#include <cstdint>
#include <math.h>

#define BD   2
#define SD   2048
#define DD   1024
#define HH   16
#define DHH  64
#define FFD  4096
#define NR   (BD*SD)              // 4096 rows
#define QKVD 3072
#define NEGV (-1000000000.0f)

// ---------------- scratch (static device globals; no allocation allowed) ----
__device__ float g_x   [NR*DD];             // fp32 residual stream
__device__ float g_xt  [NR*DD];             // tf32 shadow of LN1 out
__device__ float g_qkv [(size_t)NR*QKVD];   // fused Q|K|V, tf32 bits
__device__ float g_att [NR*DD];             // tf32 bits
__device__ float g_ao  [NR*DD];             // fp32
__device__ float g_xn  [NR*DD];             // tf32 bits (LN3 out)
__device__ float g_h   [(size_t)NR*FFD];    // tf32 bits (gelu out)
__device__ float g_pad [NR];
__device__ float g_wqkv[(size_t)QKVD*DD];   // tf32 bits
__device__ float g_bqkv[QKVD];
__device__ float g_wo  [DD*DD];             // tf32 bits
__device__ float g_w1  [(size_t)DD*FFD];    // tf32 bits
__device__ float g_w2  [(size_t)DD*FFD];    // tf32 bits

// ---------------- tf32 / mma helpers ----------------------------------------
__device__ __forceinline__ float gelu_f(float x) {
    return 0.5f * x * (1.0f + erff(x * 0.70710678118654752f));
}
__device__ __forceinline__ uint32_t f2tf32(float x) {
    uint32_t t;
    asm("cvt.rna.tf32.f32 %0, %1;" : "=r"(t) : "f"(x));
    return t;
}
__device__ __forceinline__ void mma1688(float* c, const uint32_t* a, const uint32_t* b) {
    asm volatile(
        "mma.sync.aligned.m16n8k8.row.col.f32.tf32.tf32.f32 "
        "{%0,%1,%2,%3}, {%4,%5,%6,%7}, {%8,%9}, {%0,%1,%2,%3};"
        : "+f"(c[0]), "+f"(c[1]), "+f"(c[2]), "+f"(c[3])
        : "r"(a[0]), "r"(a[1]), "r"(a[2]), "r"(a[3]), "r"(b[0]), "r"(b[1]));
}
__device__ __forceinline__ uint32_t smem_u32(const void* p) {
    uint32_t a;
    asm("{ .reg .u64 t; cvta.to.shared.u64 t, %1; cvt.u32.u64 %0, t; }"
        : "=r"(a) : "l"(p));
    return a;
}
#define LDSM4(r0, r1, r2, r3, addr) \
    asm volatile("ldmatrix.sync.aligned.m8n8.x4.shared.b16 {%0,%1,%2,%3}, [%4];" \
                 : "=r"(r0), "=r"(r1), "=r"(r2), "=r"(r3) : "r"(addr))

__device__ __forceinline__ float warpSum(float v) {
    #pragma unroll
    for (int o = 16; o; o >>= 1) v += __shfl_xor_sync(0xffffffffu, v, o);
    return v;
}

// ------- K1: embedding + pos + LN1 -> g_x, g_xt ; pad mask (warp/row) -------
__global__ void embed_ln_k(const int* __restrict__ tok,
                           const float* __restrict__ emb,
                           const float* __restrict__ pos,
                           const float* __restrict__ gam,
                           const float* __restrict__ bet) {
    int w = threadIdx.x >> 5, lane = threadIdx.x & 31;
    int n = blockIdx.x * 8 + w;
    int t = tok[n];
    int s = n & (SD - 1);
    float4 v[8];
    float sum = 0.0f;
    #pragma unroll
    for (int q = 0; q < 8; q++) {
        int c = (q * 32 + lane) * 4;
        float4 e = *(const float4*)(emb + (size_t)t * DD + c);
        float4 p = *(const float4*)(pos + (size_t)s * DD + c);
        v[q].x = e.x + p.x; v[q].y = e.y + p.y;
        v[q].z = e.z + p.z; v[q].w = e.w + p.w;
        sum += v[q].x + v[q].y + v[q].z + v[q].w;
    }
    float mean = warpSum(sum) * (1.0f / DD);
    float vs = 0.0f;
    #pragma unroll
    for (int q = 0; q < 8; q++) {
        float d0 = v[q].x - mean, d1 = v[q].y - mean;
        float d2 = v[q].z - mean, d3 = v[q].w - mean;
        vs += d0*d0 + d1*d1 + d2*d2 + d3*d3;
    }
    float rs = rsqrtf(warpSum(vs) * (1.0f / DD) + 1e-5f);
    #pragma unroll
    for (int q = 0; q < 8; q++) {
        int c = (q * 32 + lane) * 4;
        float4 gg = *(const float4*)(gam + c);
        float4 bb = *(const float4*)(bet + c);
        float4 o;
        o.x = (v[q].x - mean) * rs * gg.x + bb.x;
        o.y = (v[q].y - mean) * rs * gg.y + bb.y;
        o.z = (v[q].z - mean) * rs * gg.z + bb.z;
        o.w = (v[q].w - mean) * rs * gg.w + bb.w;
        *(float4*)(g_x + (size_t)n * DD + c) = o;
        uint4 ot = make_uint4(f2tf32(o.x), f2tf32(o.y), f2tf32(o.z), f2tf32(o.w));
        *(uint4*)(g_xt + (size_t)n * DD + c) = ot;
    }
    if (lane == 0) g_pad[n] = (t == 0) ? NEGV : 0.0f;
}

// -- fused LN2+LN3 (warp/row): g_x += LN2(g_ao); g_xn = tf32(LN3(g_x)) -------
__global__ void ln23_k(const float* __restrict__ g2, const float* __restrict__ b2v,
                       const float* __restrict__ g3, const float* __restrict__ b3v) {
    int w = threadIdx.x >> 5, lane = threadIdx.x & 31;
    int n = blockIdx.x * 8 + w;
    float4 a[8], x[8];
    float sum = 0.0f;
    #pragma unroll
    for (int q = 0; q < 8; q++) {
        int c = (q * 32 + lane) * 4;
        a[q] = *(const float4*)(g_ao + (size_t)n * DD + c);
        sum += a[q].x + a[q].y + a[q].z + a[q].w;
    }
    float mean = warpSum(sum) * (1.0f / DD);
    float vs = 0.0f;
    #pragma unroll
    for (int q = 0; q < 8; q++) {
        float d0 = a[q].x - mean, d1 = a[q].y - mean;
        float d2 = a[q].z - mean, d3 = a[q].w - mean;
        vs += d0*d0 + d1*d1 + d2*d2 + d3*d3;
    }
    float rs = rsqrtf(warpSum(vs) * (1.0f / DD) + 1e-5f);
    float sum3 = 0.0f;
    #pragma unroll
    for (int q = 0; q < 8; q++) {
        int c = (q * 32 + lane) * 4;
        float4 gg = *(const float4*)(g2 + c);
        float4 bb = *(const float4*)(b2v + c);
        x[q] = *(const float4*)(g_x + (size_t)n * DD + c);
        x[q].x += (a[q].x - mean) * rs * gg.x + bb.x;
        x[q].y += (a[q].y - mean) * rs * gg.y + bb.y;
        x[q].z += (a[q].z - mean) * rs * gg.z + bb.z;
        x[q].w += (a[q].w - mean) * rs * gg.w + bb.w;
        *(float4*)(g_x + (size_t)n * DD + c) = x[q];
        sum3 += x[q].x + x[q].y + x[q].z + x[q].w;
    }
    float mean3 = warpSum(sum3) * (1.0f / DD);
    float vs3 = 0.0f;
    #pragma unroll
    for (int q = 0; q < 8; q++) {
        float d0 = x[q].x - mean3, d1 = x[q].y - mean3;
        float d2 = x[q].z - mean3, d3 = x[q].w - mean3;
        vs3 += d0*d0 + d1*d1 + d2*d2 + d3*d3;
    }
    float rs3 = rsqrtf(warpSum(vs3) * (1.0f / DD) + 1e-5f);
    #pragma unroll
    for (int q = 0; q < 8; q++) {
        int c = (q * 32 + lane) * 4;
        float4 gg = *(const float4*)(g3 + c);
        float4 bb = *(const float4*)(b3v + c);
        uint4 o = make_uint4(f2tf32((x[q].x - mean3) * rs3 * gg.x + bb.x),
                             f2tf32((x[q].y - mean3) * rs3 * gg.y + bb.y),
                             f2tf32((x[q].z - mean3) * rs3 * gg.z + bb.z),
                             f2tf32((x[q].w - mean3) * rs3 * gg.w + bb.w));
        *(uint4*)(g_xn + (size_t)n * DD + c) = o;
    }
}

// ---- merged QKV+Wo transpose (+ bias pack in block 0,0,0) ------------------
__global__ void transpose_qkvo_k(const float* __restrict__ Wq,
                                 const float* __restrict__ Wk,
                                 const float* __restrict__ Wv,
                                 const float* __restrict__ Wo,
                                 const float* __restrict__ bq,
                                 const float* __restrict__ bk,
                                 const float* __restrict__ bv) {
    __shared__ float t[32][33];
    const float* in = (blockIdx.z == 0) ? Wq : (blockIdx.z == 1) ? Wk
                    : (blockIdx.z == 2) ? Wv : Wo;
    float* out = (blockIdx.z < 3) ? (g_wqkv + (size_t)blockIdx.z * DD * DD) : g_wo;
    if (blockIdx.z == 0 && blockIdx.x == 0 && blockIdx.y == 0) {
        int tid = threadIdx.y * 32 + threadIdx.x;
        for (int i = tid; i < QKVD; i += 256) {
            float v = (i < 1024) ? bq[i] : (i < 2048) ? bk[i - 1024] : bv[i - 2048];
            g_bqkv[i] = v;
        }
    }
    int bx = blockIdx.x * 32, by = blockIdx.y * 32;
    int x = bx + threadIdx.x;
    #pragma unroll
    for (int i = 0; i < 4; i++)
        t[threadIdx.y + i * 8][threadIdx.x] = in[(size_t)(by + threadIdx.y + i * 8) * DD + x];
    __syncthreads();
    int xo = by + threadIdx.x;
    #pragma unroll
    for (int i = 0; i < 4; i++)
        out[(size_t)(bx + threadIdx.y + i * 8) * DD + xo] =
            __uint_as_float(f2tf32(t[threadIdx.x][threadIdx.y + i * 8]));
}

// ---- merged W1/W2 transpose ------------------------------------------------
__global__ void transpose_w12_k(const float* __restrict__ W1,
                                const float* __restrict__ W2) {
    __shared__ float t[32][33];
    int z = blockIdx.z;
    const float* in = z ? W2 : W1;
    float* out = z ? g_w2 : g_w1;
    int Cc = z ? DD : FFD;
    int R  = z ? FFD : DD;
    int bxi = z ? blockIdx.y : blockIdx.x;
    int byi = z ? blockIdx.x : blockIdx.y;
    int bx = bxi * 32, by = byi * 32;
    int x = bx + threadIdx.x;
    #pragma unroll
    for (int i = 0; i < 4; i++)
        t[threadIdx.y + i * 8][threadIdx.x] = in[(size_t)(by + threadIdx.y + i * 8) * Cc + x];
    __syncthreads();
    int xo = by + threadIdx.x;
    #pragma unroll
    for (int i = 0; i < 4; i++)
        out[(size_t)(bx + threadIdx.y + i * 8) * R + xo] =
            __uint_as_float(f2tf32(t[threadIdx.x][threadIdx.y + i * 8]));
}

// ------ mma.sync tf32 GEMM, double-buffered LDG prefetch + ldmatrix ---------
#define SSTR 36
#define SBUF (128 * SSTR)
#define GEMM_SMEM (2 * 2 * SBUF * 4)       // 73728 bytes

template <int EPI>
__global__ __launch_bounds__(256, 2)
void tc_gemm(const float* __restrict__ A, const float* __restrict__ Bt,
             const float* __restrict__ bias, float* __restrict__ C,
             int K, int Mout, const float* __restrict__ res) {
    extern __shared__ uint32_t dsm[];

    int tid  = threadIdx.x;
    int wid  = tid >> 5;
    int lane = tid & 31;
    int wm   = wid >> 1;
    int wn   = wid & 1;
    int gq   = lane >> 2;
    int tg   = lane & 3;

    int r  = tid >> 1;
    int cb = (tid & 1) * 16;
    const float* ArowP = A  + (size_t)(blockIdx.y * 128 + r) * K + cb;
    const float* BrowP = Bt + (size_t)(blockIdx.x * 128 + r) * K + cb;
    uint32_t rowoff = r * SSTR + cb;
    uint32_t sbase = smem_u32(dsm);

    uint32_t aoffB[2], boffB[4];
    #pragma unroll
    for (int mt = 0; mt < 2; mt++)
        aoffB[mt] = ((wm * 32 + mt * 16 + (lane & 15)) * SSTR + ((lane >> 4) << 2)) * 4;
    #pragma unroll
    for (int p = 0; p < 4; p++)
        boffB[p] = (SBUF + (wn * 64 + p * 16 + ((lane >> 4) << 3) + (lane & 7)) * SSTR
                    + (((lane >> 3) & 1) << 2)) * 4;

    float acc[2][8][4];
    #pragma unroll
    for (int mt = 0; mt < 2; mt++)
        #pragma unroll
        for (int nt = 0; nt < 8; nt++)
            #pragma unroll
            for (int c = 0; c < 4; c++) acc[mt][nt][c] = 0.0f;

    int NC = K >> 5;
    uint4 pa[4], pb[4];
    #pragma unroll
    for (int q = 0; q < 4; q++) {
        pa[q] = *(const uint4*)(ArowP + q * 4);
        pb[q] = *(const uint4*)(BrowP + q * 4);
    }
    {
        uint32_t* dA = dsm + rowoff;
        uint32_t* dB = dA + SBUF;
        #pragma unroll
        for (int q = 0; q < 4; q++) {
            *(uint4*)(dA + q * 4) = pa[q];
            *(uint4*)(dB + q * 4) = pb[q];
        }
    }
    __syncthreads();

    for (int i = 0; i < NC; i++) {
        uint32_t bufbase = sbase + (i & 1) * (2 * SBUF * 4);
        if (i + 1 < NC) {
            #pragma unroll
            for (int q = 0; q < 4; q++) {
                pa[q] = *(const uint4*)(ArowP + (i + 1) * 32 + q * 4);
                pb[q] = *(const uint4*)(BrowP + (i + 1) * 32 + q * 4);
            }
        }
        #pragma unroll
        for (int ks = 0; ks < 4; ks++) {
            uint32_t kb = ks * 32;
            uint32_t af[2][4], bf[8][2];
            LDSM4(af[0][0], af[0][1], af[0][2], af[0][3], bufbase + aoffB[0] + kb);
            LDSM4(af[1][0], af[1][1], af[1][2], af[1][3], bufbase + aoffB[1] + kb);
            LDSM4(bf[0][0], bf[0][1], bf[1][0], bf[1][1], bufbase + boffB[0] + kb);
            LDSM4(bf[2][0], bf[2][1], bf[3][0], bf[3][1], bufbase + boffB[1] + kb);
            LDSM4(bf[4][0], bf[4][1], bf[5][0], bf[5][1], bufbase + boffB[2] + kb);
            LDSM4(bf[6][0], bf[6][1], bf[7][0], bf[7][1], bufbase + boffB[3] + kb);
            #pragma unroll
            for (int mt = 0; mt < 2; mt++)
                #pragma unroll
                for (int nt = 0; nt < 8; nt++)
                    mma1688(acc[mt][nt], af[mt], bf[nt]);
        }
        if (i + 1 < NC) {
            uint32_t* dA = dsm + ((i + 1) & 1) * 2 * SBUF + rowoff;
            uint32_t* dB = dA + SBUF;
            #pragma unroll
            for (int q = 0; q < 4; q++) {
                *(uint4*)(dA + q * 4) = pa[q];
                *(uint4*)(dB + q * 4) = pb[q];
            }
        }
        __syncthreads();
    }

    #pragma unroll
    for (int mt = 0; mt < 2; mt++) {
        #pragma unroll
        for (int nt = 0; nt < 8; nt++) {
            int col = blockIdx.x * 128 + wn * 64 + nt * 8 + 2 * tg;
            float2 bb = *(const float2*)(bias + col);
            #pragma unroll
            for (int h = 0; h < 2; h++) {
                int row = blockIdx.y * 128 + wm * 32 + mt * 16 + gq + h * 8;
                size_t off = (size_t)row * Mout + col;
                float2 o;
                o.x = acc[mt][nt][2 * h + 0] + bb.x;
                o.y = acc[mt][nt][2 * h + 1] + bb.y;
                if (EPI == 1) { o.x = gelu_f(o.x); o.y = gelu_f(o.y); }
                if (EPI == 2) {
                    float2 rr = *(const float2*)(res + off);
                    o.x += rr.x; o.y += rr.y;
                }
                if (EPI == 1 || EPI == 3) {
                    o.x = __uint_as_float(f2tf32(o.x));
                    o.y = __uint_as_float(f2tf32(o.y));
                }
                *(float2*)(C + off) = o;
            }
        }
    }
}

// ---------------- tensor-core flash attention (tf32) ------------------------
// 128 queries/CTA, 8 warps x 16 queries, key tiles 64. 2 CTAs/SM.
// sK stride 68 (ldmatrix conflict-free); sV stride 72 (scalar LDS conflict-free)
#define ASTR 68
#define VSTR 72

__device__ __forceinline__ void quad_permute(uint32_t p0, uint32_t p1, int lane,
                                             uint32_t& a_lo, uint32_t& a_hi) {
    int tg = lane & 3;
    int base = lane & ~3;
    int l1 = base + (tg >> 1);
    int l2 = base + 2 + (tg >> 1);
    uint32_t s0a = __shfl_sync(0xffffffffu, p0, l1);
    uint32_t s1a = __shfl_sync(0xffffffffu, p1, l1);
    uint32_t s0b = __shfl_sync(0xffffffffu, p0, l2);
    uint32_t s1b = __shfl_sync(0xffffffffu, p1, l2);
    a_lo = (tg & 1) ? s1a : s0a;
    a_hi = (tg & 1) ? s1b : s0b;
}

__global__ __launch_bounds__(256, 2)
void attn_tc() {
    __shared__ uint32_t sK[64 * ASTR];
    __shared__ uint32_t sV[64 * VSTR];
    __shared__ float sPad[64];

    int qt = (gridDim.x - 1) - blockIdx.x;  // longest CTAs first
    int bh = blockIdx.y;
    int b = bh >> 4, h = bh & 15;
    int tid = threadIdx.x;
    int lane = tid & 31;
    int w = tid >> 5;
    int gq = lane >> 2, tg = lane & 3;
    int qabs0 = qt * 128 + w * 16;

    // ldmatrix byte-offsets for K fragments
    uint32_t koffB[4];
    #pragma unroll
    for (int p = 0; p < 4; p++)
        koffB[p] = ((p * 16 + ((lane >> 4) << 3) + (lane & 7)) * ASTR
                    + (((lane >> 3) & 1) << 2)) * 4;
    uint32_t skb = smem_u32(sK);

    // Q fragments (g_qkv already tf32 bits)
    uint32_t qa[8][4];
    const float* Qb = g_qkv + ((size_t)(b * SD) + qabs0) * QKVD + h * DHH;
    #pragma unroll
    for (int ks = 0; ks < 8; ks++) {
        qa[ks][0] = __float_as_uint(Qb[(size_t)gq * QKVD + ks * 8 + tg]);
        qa[ks][1] = __float_as_uint(Qb[(size_t)(gq + 8) * QKVD + ks * 8 + tg]);
        qa[ks][2] = __float_as_uint(Qb[(size_t)gq * QKVD + ks * 8 + tg + 4]);
        qa[ks][3] = __float_as_uint(Qb[(size_t)(gq + 8) * QKVD + ks * 8 + tg + 4]);
    }

    float m0 = -1e30f, m1 = -1e30f, l0 = 0.0f, l1 = 0.0f;
    float Oa[8][4];
    #pragma unroll
    for (int nt = 0; nt < 8; nt++)
        #pragma unroll
        for (int c = 0; c < 4; c++) Oa[nt][c] = 0.0f;

    int lr = tid >> 2;              // 0..63
    int lc = (tid & 3) * 16;        // 0,16,32,48

    int KBMAX = 2 * qt + 1;
    for (int kb = 0; kb <= KBMAX; kb++) {
        size_t gb = ((size_t)(b * SD) + kb * 64 + lr) * QKVD + h * DHH + lc;
        uint32_t* kRow = sK + lr * ASTR + lc;
        uint32_t* vRow = sV + lr * VSTR + lc;
        #pragma unroll
        for (int q = 0; q < 4; q++) {
            *(uint4*)(kRow + q * 4) = *(const uint4*)(g_qkv + gb + 1024 + q * 4);
            *(uint4*)(vRow + q * 4) = *(const uint4*)(g_qkv + gb + 2048 + q * 4);
        }
        if (tid < 64) sPad[tid] = g_pad[(size_t)b * SD + kb * 64 + tid];
        __syncthreads();

        if (kb * 64 <= qabs0 + 15) {            // warp-uniform causal skip
            float sv[8][4];
            #pragma unroll
            for (int nt = 0; nt < 8; nt++)
                #pragma unroll
                for (int c = 0; c < 4; c++) sv[nt][c] = 0.0f;
            #pragma unroll
            for (int ks = 0; ks < 8; ks++) {
                uint32_t kf[8][2];
                uint32_t kbo = ks * 32;
                LDSM4(kf[0][0], kf[0][1], kf[1][0], kf[1][1], skb + koffB[0] + kbo);
                LDSM4(kf[2][0], kf[2][1], kf[3][0], kf[3][1], skb + koffB[1] + kbo);
                LDSM4(kf[4][0], kf[4][1], kf[5][0], kf[5][1], skb + koffB[2] + kbo);
                LDSM4(kf[6][0], kf[6][1], kf[7][0], kf[7][1], skb + koffB[3] + kbo);
                #pragma unroll
                for (int nt = 0; nt < 8; nt++)
                    mma1688(sv[nt], qa[ks], kf[nt]);
            }
            int q0 = qabs0 + gq, q1 = q0 + 8;
            float mx0 = -1e30f, mx1 = -1e30f;
            #pragma unroll
            for (int nt = 0; nt < 8; nt++) {
                int kc = kb * 64 + nt * 8 + 2 * tg;
                float pad0 = sPad[nt * 8 + 2 * tg];
                float pad1 = sPad[nt * 8 + 2 * tg + 1];
                sv[nt][0] = sv[nt][0] * 0.125f + pad0 + ((kc     > q0) ? NEGV : 0.0f);
                sv[nt][1] = sv[nt][1] * 0.125f + pad1 + ((kc + 1 > q0) ? NEGV : 0.0f);
                sv[nt][2] = sv[nt][2] * 0.125f + pad0 + ((kc     > q1) ? NEGV : 0.0f);
                sv[nt][3] = sv[nt][3] * 0.125f + pad1 + ((kc + 1 > q1) ? NEGV : 0.0f);
                mx0 = fmaxf(mx0, fmaxf(sv[nt][0], sv[nt][1]));
                mx1 = fmaxf(mx1, fmaxf(sv[nt][2], sv[nt][3]));
            }
            mx0 = fmaxf(mx0, __shfl_xor_sync(0xffffffffu, mx0, 1));
            mx0 = fmaxf(mx0, __shfl_xor_sync(0xffffffffu, mx0, 2));
            mx1 = fmaxf(mx1, __shfl_xor_sync(0xffffffffu, mx1, 1));
            mx1 = fmaxf(mx1, __shfl_xor_sync(0xffffffffu, mx1, 2));
            float mn0 = fmaxf(m0, mx0), mn1 = fmaxf(m1, mx1);
            float cr0 = __expf(m0 - mn0), cr1 = __expf(m1 - mn1);
            m0 = mn0; m1 = mn1;

            float rs0 = 0.0f, rs1 = 0.0f;
            #pragma unroll
            for (int nt = 0; nt < 8; nt++) {
                float p0 = __expf(sv[nt][0] - mn0);
                float p1 = __expf(sv[nt][1] - mn0);
                float p2 = __expf(sv[nt][2] - mn1);
                float p3 = __expf(sv[nt][3] - mn1);
                rs0 += p0 + p1; rs1 += p2 + p3;
                uint32_t w0, w1c, w2, w3;
                quad_permute(f2tf32(p0), f2tf32(p1), lane, w0, w2);
                quad_permute(f2tf32(p2), f2tf32(p3), lane, w1c, w3);
                sv[nt][0] = __uint_as_float(w0);
                sv[nt][1] = __uint_as_float(w1c);
                sv[nt][2] = __uint_as_float(w2);
                sv[nt][3] = __uint_as_float(w3);
            }
            rs0 += __shfl_xor_sync(0xffffffffu, rs0, 1);
            rs0 += __shfl_xor_sync(0xffffffffu, rs0, 2);
            rs1 += __shfl_xor_sync(0xffffffffu, rs1, 1);
            rs1 += __shfl_xor_sync(0xffffffffu, rs1, 2);
            l0 = l0 * cr0 + rs0;
            l1 = l1 * cr1 + rs1;
            #pragma unroll
            for (int nt = 0; nt < 8; nt++) {
                Oa[nt][0] *= cr0; Oa[nt][1] *= cr0;
                Oa[nt][2] *= cr1; Oa[nt][3] *= cr1;
            }
            #pragma unroll
            for (int ks = 0; ks < 8; ks++) {
                uint32_t pf[4] = { __float_as_uint(sv[ks][0]), __float_as_uint(sv[ks][1]),
                                   __float_as_uint(sv[ks][2]), __float_as_uint(sv[ks][3]) };
                #pragma unroll
                for (int nt = 0; nt < 8; nt++) {
                    const uint32_t* vp = sV + (ks * 8 + tg) * VSTR + nt * 8 + gq;
                    uint32_t bv[2] = { vp[0], vp[4 * VSTR] };
                    mma1688(Oa[nt], pf, bv);
                }
            }
        }
        __syncthreads();
    }

    float inv0 = 1.0f / l0, inv1 = 1.0f / l1;
    size_t o0 = ((size_t)(b * SD) + qabs0 + gq) * DD + h * DHH + 2 * tg;
    size_t o1 = o0 + (size_t)8 * DD;
    #pragma unroll
    for (int nt = 0; nt < 8; nt++) {
        *(float2*)(g_att + o0 + nt * 8) =
            make_float2(__uint_as_float(f2tf32(Oa[nt][0] * inv0)),
                        __uint_as_float(f2tf32(Oa[nt][1] * inv0)));
        *(float2*)(g_att + o1 + nt * 8) =
            make_float2(__uint_as_float(f2tf32(Oa[nt][2] * inv1)),
                        __uint_as_float(f2tf32(Oa[nt][3] * inv1)));
    }
}

// ---------------- launch --------------------------------------------------
extern "C" void kernel_launch(void* const* d_in, const int* in_sizes, int n_in,
                              void* d_out, int out_size) {
    const int*   tokens = (const int*)  d_in[0];
    const float* emb    = (const float*)d_in[1];
    const float* pos    = (const float*)d_in[2];
    const float* ln1_g  = (const float*)d_in[3];
    const float* ln1_b  = (const float*)d_in[4];
    const float* ln2_g  = (const float*)d_in[5];
    const float* ln2_b  = (const float*)d_in[6];
    const float* ln3_g  = (const float*)d_in[7];
    const float* ln3_b  = (const float*)d_in[8];
    const float* Wq     = (const float*)d_in[9];
    const float* bq     = (const float*)d_in[10];
    const float* Wk     = (const float*)d_in[11];
    const float* bk     = (const float*)d_in[12];
    const float* Wv     = (const float*)d_in[13];
    const float* bv     = (const float*)d_in[14];
    const float* Wo     = (const float*)d_in[15];
    const float* bo     = (const float*)d_in[16];
    const float* W1     = (const float*)d_in[17];
    const float* b1     = (const float*)d_in[18];
    const float* W2     = (const float*)d_in[19];
    const float* b2     = (const float*)d_in[20];
    float* out = (float*)d_out;

    float *xp, *xtp, *qkvp, *attp, *aop, *xnp, *hp;
    float *wqkvp, *bqkvp, *wop, *w1p, *w2p;
    cudaGetSymbolAddress((void**)&xp,    g_x);
    cudaGetSymbolAddress((void**)&xtp,   g_xt);
    cudaGetSymbolAddress((void**)&qkvp,  g_qkv);
    cudaGetSymbolAddress((void**)&attp,  g_att);
    cudaGetSymbolAddress((void**)&aop,   g_ao);
    cudaGetSymbolAddress((void**)&xnp,   g_xn);
    cudaGetSymbolAddress((void**)&hp,    g_h);
    cudaGetSymbolAddress((void**)&wqkvp, g_wqkv);
    cudaGetSymbolAddress((void**)&bqkvp, g_bqkv);
    cudaGetSymbolAddress((void**)&wop,   g_wo);
    cudaGetSymbolAddress((void**)&w1p,   g_w1);
    cudaGetSymbolAddress((void**)&w2p,   g_w2);

    static bool attr_done = false;
    if (!attr_done) {
        cudaFuncSetAttribute(tc_gemm<0>, cudaFuncAttributeMaxDynamicSharedMemorySize, GEMM_SMEM);
        cudaFuncSetAttribute(tc_gemm<1>, cudaFuncAttributeMaxDynamicSharedMemorySize, GEMM_SMEM);
        cudaFuncSetAttribute(tc_gemm<2>, cudaFuncAttributeMaxDynamicSharedMemorySize, GEMM_SMEM);
        cudaFuncSetAttribute(tc_gemm<3>, cudaFuncAttributeMaxDynamicSharedMemorySize, GEMM_SMEM);
        attr_done = true;
    }

    dim3 tb(32, 8);
    embed_ln_k<<<NR / 8, 256>>>(tokens, emb, pos, ln1_g, ln1_b);
    transpose_qkvo_k<<<dim3(DD / 32, DD / 32, 4), tb>>>(Wq, Wk, Wv, Wo, bq, bk, bv);
    transpose_w12_k<<<dim3(FFD / 32, DD / 32, 2), tb>>>(W1, W2);

    // fused QKV projection (tf32-rounded output)
    tc_gemm<3><<<dim3(QKVD / 128, NR / 128), 256, GEMM_SMEM>>>(xtp, wqkvp, bqkvp, qkvp, DD, QKVD, nullptr);

    attn_tc<<<dim3(SD / 128, BD * HH), 256>>>();

    tc_gemm<0><<<dim3(DD / 128, NR / 128), 256, GEMM_SMEM>>>(attp, wop, bo, aop, DD, DD, nullptr);
    ln23_k<<<NR / 8, 256>>>(ln2_g, ln2_b, ln3_g, ln3_b);

    tc_gemm<1><<<dim3(FFD / 128, NR / 128), 256, GEMM_SMEM>>>(xnp, w1p, b1, hp, DD, FFD, nullptr);
    tc_gemm<2><<<dim3(DD / 128, NR / 128), 256, GEMM_SMEM>>>(hp, w2p, b2, out, FFD, DD, xp);
}

// round 16
// speedup vs baseline: 1.1027x; 1.0461x over previous
#include <cuda_runtime.h>
#include <cstdint>
#include <math.h>

#define BD   2
#define SD   2048
#define DD   1024
#define HH   16
#define DHH  64
#define FFD  4096
#define NR   (BD*SD)              // 4096 rows
#define QKVD 3072
#define NEGV (-1000000000.0f)

// ---------------- scratch (static device globals; no allocation allowed) ----
__device__ float g_x   [NR*DD];             // fp32 residual stream
__device__ float g_xt  [NR*DD];             // tf32 shadow of LN1 out
__device__ float g_qkv [(size_t)NR*QKVD];   // fused Q|K|V, tf32 bits
__device__ float g_att [NR*DD];             // tf32 bits
__device__ float g_ao  [NR*DD];             // fp32
__device__ float g_xn  [NR*DD];             // tf32 bits (LN3 out)
__device__ float g_h   [(size_t)NR*FFD];    // tf32 bits (gelu out)
__device__ float g_pad [NR];
__device__ float g_wqkv[(size_t)QKVD*DD];   // tf32 bits
__device__ float g_bqkv[QKVD];
__device__ float g_wo  [DD*DD];             // tf32 bits
__device__ float g_w1  [(size_t)DD*FFD];    // tf32 bits
__device__ float g_w2  [(size_t)DD*FFD];    // tf32 bits

// ---------------- tf32 / mma helpers ----------------------------------------
__device__ __forceinline__ float gelu_f(float x) {
    return 0.5f * x * (1.0f + erff(x * 0.70710678118654752f));
}
__device__ __forceinline__ uint32_t f2tf32(float x) {
    uint32_t t;
    asm("cvt.rna.tf32.f32 %0, %1;" : "=r"(t) : "f"(x));
    return t;
}
__device__ __forceinline__ void mma1688(float* c, const uint32_t* a, const uint32_t* b) {
    asm volatile(
        "mma.sync.aligned.m16n8k8.row.col.f32.tf32.tf32.f32 "
        "{%0,%1,%2,%3}, {%4,%5,%6,%7}, {%8,%9}, {%0,%1,%2,%3};"
        : "+f"(c[0]), "+f"(c[1]), "+f"(c[2]), "+f"(c[3])
        : "r"(a[0]), "r"(a[1]), "r"(a[2]), "r"(a[3]), "r"(b[0]), "r"(b[1]));
}
__device__ __forceinline__ uint32_t smem_u32(const void* p) {
    uint32_t a;
    asm("{ .reg .u64 t; cvta.to.shared.u64 t, %1; cvt.u32.u64 %0, t; }"
        : "=r"(a) : "l"(p));
    return a;
}
#define LDSM4(r0, r1, r2, r3, addr) \
    asm volatile("ldmatrix.sync.aligned.m8n8.x4.shared.b16 {%0,%1,%2,%3}, [%4];" \
                 : "=r"(r0), "=r"(r1), "=r"(r2), "=r"(r3) : "r"(addr))

__device__ __forceinline__ float warpSum(float v) {
    #pragma unroll
    for (int o = 16; o; o >>= 1) v += __shfl_xor_sync(0xffffffffu, v, o);
    return v;
}

// ------- K1: embedding + pos + LN1 -> g_x, g_xt ; pad mask (warp/row) -------
__global__ void embed_ln_k(const int* __restrict__ tok,
                           const float* __restrict__ emb,
                           const float* __restrict__ pos,
                           const float* __restrict__ gam,
                           const float* __restrict__ bet) {
    int w = threadIdx.x >> 5, lane = threadIdx.x & 31;
    int n = blockIdx.x * 8 + w;
    int t = tok[n];
    int s = n & (SD - 1);
    float4 v[8];
    float sum = 0.0f;
    #pragma unroll
    for (int q = 0; q < 8; q++) {
        int c = (q * 32 + lane) * 4;
        float4 e = *(const float4*)(emb + (size_t)t * DD + c);
        float4 p = *(const float4*)(pos + (size_t)s * DD + c);
        v[q].x = e.x + p.x; v[q].y = e.y + p.y;
        v[q].z = e.z + p.z; v[q].w = e.w + p.w;
        sum += v[q].x + v[q].y + v[q].z + v[q].w;
    }
    float mean = warpSum(sum) * (1.0f / DD);
    float vs = 0.0f;
    #pragma unroll
    for (int q = 0; q < 8; q++) {
        float d0 = v[q].x - mean, d1 = v[q].y - mean;
        float d2 = v[q].z - mean, d3 = v[q].w - mean;
        vs += d0*d0 + d1*d1 + d2*d2 + d3*d3;
    }
    float rs = rsqrtf(warpSum(vs) * (1.0f / DD) + 1e-5f);
    #pragma unroll
    for (int q = 0; q < 8; q++) {
        int c = (q * 32 + lane) * 4;
        float4 gg = *(const float4*)(gam + c);
        float4 bb = *(const float4*)(bet + c);
        float4 o;
        o.x = (v[q].x - mean) * rs * gg.x + bb.x;
        o.y = (v[q].y - mean) * rs * gg.y + bb.y;
        o.z = (v[q].z - mean) * rs * gg.z + bb.z;
        o.w = (v[q].w - mean) * rs * gg.w + bb.w;
        *(float4*)(g_x + (size_t)n * DD + c) = o;
        uint4 ot = make_uint4(f2tf32(o.x), f2tf32(o.y), f2tf32(o.z), f2tf32(o.w));
        *(uint4*)(g_xt + (size_t)n * DD + c) = ot;
    }
    if (lane == 0) g_pad[n] = (t == 0) ? NEGV : 0.0f;
}

// -- fused LN2+LN3 (warp/row): g_x += LN2(g_ao); g_xn = tf32(LN3(g_x)) -------
__global__ void ln23_k(const float* __restrict__ g2, const float* __restrict__ b2v,
                       const float* __restrict__ g3, const float* __restrict__ b3v) {
    int w = threadIdx.x >> 5, lane = threadIdx.x & 31;
    int n = blockIdx.x * 8 + w;
    float4 a[8], x[8];
    float sum = 0.0f;
    #pragma unroll
    for (int q = 0; q < 8; q++) {
        int c = (q * 32 + lane) * 4;
        a[q] = *(const float4*)(g_ao + (size_t)n * DD + c);
        sum += a[q].x + a[q].y + a[q].z + a[q].w;
    }
    float mean = warpSum(sum) * (1.0f / DD);
    float vs = 0.0f;
    #pragma unroll
    for (int q = 0; q < 8; q++) {
        float d0 = a[q].x - mean, d1 = a[q].y - mean;
        float d2 = a[q].z - mean, d3 = a[q].w - mean;
        vs += d0*d0 + d1*d1 + d2*d2 + d3*d3;
    }
    float rs = rsqrtf(warpSum(vs) * (1.0f / DD) + 1e-5f);
    float sum3 = 0.0f;
    #pragma unroll
    for (int q = 0; q < 8; q++) {
        int c = (q * 32 + lane) * 4;
        float4 gg = *(const float4*)(g2 + c);
        float4 bb = *(const float4*)(b2v + c);
        x[q] = *(const float4*)(g_x + (size_t)n * DD + c);
        x[q].x += (a[q].x - mean) * rs * gg.x + bb.x;
        x[q].y += (a[q].y - mean) * rs * gg.y + bb.y;
        x[q].z += (a[q].z - mean) * rs * gg.z + bb.z;
        x[q].w += (a[q].w - mean) * rs * gg.w + bb.w;
        *(float4*)(g_x + (size_t)n * DD + c) = x[q];
        sum3 += x[q].x + x[q].y + x[q].z + x[q].w;
    }
    float mean3 = warpSum(sum3) * (1.0f / DD);
    float vs3 = 0.0f;
    #pragma unroll
    for (int q = 0; q < 8; q++) {
        float d0 = x[q].x - mean3, d1 = x[q].y - mean3;
        float d2 = x[q].z - mean3, d3 = x[q].w - mean3;
        vs3 += d0*d0 + d1*d1 + d2*d2 + d3*d3;
    }
    float rs3 = rsqrtf(warpSum(vs3) * (1.0f / DD) + 1e-5f);
    #pragma unroll
    for (int q = 0; q < 8; q++) {
        int c = (q * 32 + lane) * 4;
        float4 gg = *(const float4*)(g3 + c);
        float4 bb = *(const float4*)(b3v + c);
        uint4 o = make_uint4(f2tf32((x[q].x - mean3) * rs3 * gg.x + bb.x),
                             f2tf32((x[q].y - mean3) * rs3 * gg.y + bb.y),
                             f2tf32((x[q].z - mean3) * rs3 * gg.z + bb.z),
                             f2tf32((x[q].w - mean3) * rs3 * gg.w + bb.w));
        *(uint4*)(g_xn + (size_t)n * DD + c) = o;
    }
}

// ---- merged QKV+Wo transpose (+ bias pack in block 0,0,0) ------------------
__global__ void transpose_qkvo_k(const float* __restrict__ Wq,
                                 const float* __restrict__ Wk,
                                 const float* __restrict__ Wv,
                                 const float* __restrict__ Wo,
                                 const float* __restrict__ bq,
                                 const float* __restrict__ bk,
                                 const float* __restrict__ bv) {
    __shared__ float t[32][33];
    const float* in = (blockIdx.z == 0) ? Wq : (blockIdx.z == 1) ? Wk
                    : (blockIdx.z == 2) ? Wv : Wo;
    float* out = (blockIdx.z < 3) ? (g_wqkv + (size_t)blockIdx.z * DD * DD) : g_wo;
    if (blockIdx.z == 0 && blockIdx.x == 0 && blockIdx.y == 0) {
        int tid = threadIdx.y * 32 + threadIdx.x;
        for (int i = tid; i < QKVD; i += 256) {
            float v = (i < 1024) ? bq[i] : (i < 2048) ? bk[i - 1024] : bv[i - 2048];
            g_bqkv[i] = v;
        }
    }
    int bx = blockIdx.x * 32, by = blockIdx.y * 32;
    int x = bx + threadIdx.x;
    #pragma unroll
    for (int i = 0; i < 4; i++)
        t[threadIdx.y + i * 8][threadIdx.x] = in[(size_t)(by + threadIdx.y + i * 8) * DD + x];
    __syncthreads();
    int xo = by + threadIdx.x;
    #pragma unroll
    for (int i = 0; i < 4; i++)
        out[(size_t)(bx + threadIdx.y + i * 8) * DD + xo] =
            __uint_as_float(f2tf32(t[threadIdx.x][threadIdx.y + i * 8]));
}

// ---- merged W1/W2 transpose ------------------------------------------------
__global__ void transpose_w12_k(const float* __restrict__ W1,
                                const float* __restrict__ W2) {
    __shared__ float t[32][33];
    int z = blockIdx.z;
    const float* in = z ? W2 : W1;
    float* out = z ? g_w2 : g_w1;
    int Cc = z ? DD : FFD;
    int R  = z ? FFD : DD;
    int bxi = z ? blockIdx.y : blockIdx.x;
    int byi = z ? blockIdx.x : blockIdx.y;
    int bx = bxi * 32, by = byi * 32;
    int x = bx + threadIdx.x;
    #pragma unroll
    for (int i = 0; i < 4; i++)
        t[threadIdx.y + i * 8][threadIdx.x] = in[(size_t)(by + threadIdx.y + i * 8) * Cc + x];
    __syncthreads();
    int xo = by + threadIdx.x;
    #pragma unroll
    for (int i = 0; i < 4; i++)
        out[(size_t)(bx + threadIdx.y + i * 8) * R + xo] =
            __uint_as_float(f2tf32(t[threadIdx.x][threadIdx.y + i * 8]));
}

// ------ mma.sync tf32 GEMM: 128 threads, 4 warps, 64x64 warp tiles ----------
// EPI 0: +bias fp32   EPI 1: gelu -> tf32   EPI 2: +bias+res fp32
// EPI 3: +bias -> tf32
#define SSTR 36
#define SBUF (128 * SSTR)
#define GEMM_SMEM (2 * 2 * SBUF * 4)       // 73728 bytes

template <int EPI>
__global__ __launch_bounds__(128, 2)
void tc_gemm(const float* __restrict__ A, const float* __restrict__ Bt,
             const float* __restrict__ bias, float* __restrict__ C,
             int K, int Mout, const float* __restrict__ res) {
    extern __shared__ uint32_t dsm[];

    int tid  = threadIdx.x;
    int wid  = tid >> 5;
    int lane = tid & 31;
    int wm   = wid >> 1;          // 0..1 -> rows wm*64
    int wn   = wid & 1;           // 0..1 -> cols wn*64
    int gq   = lane >> 2;
    int tg   = lane & 3;

    // staging: 2 threads per row, 16 floats each; each thread covers rows r0, r0+64
    int r0 = tid >> 1;            // 0..63
    int cb = (tid & 1) * 16;
    const float* A0 = A  + (size_t)(blockIdx.y * 128 + r0) * K + cb;
    const float* A1 = A0 + (size_t)64 * K;
    const float* B0 = Bt + (size_t)(blockIdx.x * 128 + r0) * K + cb;
    const float* B1 = B0 + (size_t)64 * K;
    uint32_t ro0 = r0 * SSTR + cb;
    uint32_t ro1 = (r0 + 64) * SSTR + cb;
    uint32_t sbase = smem_u32(dsm);

    uint32_t aoffB[4], boffB[4];
    #pragma unroll
    for (int mt = 0; mt < 4; mt++)
        aoffB[mt] = ((wm * 64 + mt * 16 + (lane & 15)) * SSTR + ((lane >> 4) << 2)) * 4;
    #pragma unroll
    for (int p = 0; p < 4; p++)
        boffB[p] = (SBUF + (wn * 64 + p * 16 + ((lane >> 4) << 3) + (lane & 7)) * SSTR
                    + (((lane >> 3) & 1) << 2)) * 4;

    float acc[4][8][4];
    #pragma unroll
    for (int mt = 0; mt < 4; mt++)
        #pragma unroll
        for (int nt = 0; nt < 8; nt++)
            #pragma unroll
            for (int c = 0; c < 4; c++) acc[mt][nt][c] = 0.0f;

    int NC = K >> 5;
    uint4 pa[8], pb[8];
    #pragma unroll
    for (int q = 0; q < 4; q++) {
        pa[q]     = *(const uint4*)(A0 + q * 4);
        pa[q + 4] = *(const uint4*)(A1 + q * 4);
        pb[q]     = *(const uint4*)(B0 + q * 4);
        pb[q + 4] = *(const uint4*)(B1 + q * 4);
    }
    {
        uint32_t* dA0 = dsm + ro0;
        uint32_t* dA1 = dsm + ro1;
        uint32_t* dB0 = dA0 + SBUF;
        uint32_t* dB1 = dA1 + SBUF;
        #pragma unroll
        for (int q = 0; q < 4; q++) {
            *(uint4*)(dA0 + q * 4) = pa[q];
            *(uint4*)(dA1 + q * 4) = pa[q + 4];
            *(uint4*)(dB0 + q * 4) = pb[q];
            *(uint4*)(dB1 + q * 4) = pb[q + 4];
        }
    }
    __syncthreads();

    for (int i = 0; i < NC; i++) {
        uint32_t bufbase = sbase + (i & 1) * (2 * SBUF * 4);
        if (i + 1 < NC) {
            #pragma unroll
            for (int q = 0; q < 4; q++) {
                pa[q]     = *(const uint4*)(A0 + (i + 1) * 32 + q * 4);
                pa[q + 4] = *(const uint4*)(A1 + (i + 1) * 32 + q * 4);
                pb[q]     = *(const uint4*)(B0 + (i + 1) * 32 + q * 4);
                pb[q + 4] = *(const uint4*)(B1 + (i + 1) * 32 + q * 4);
            }
        }
        // ks 0..1 while LDGs are in flight
        #pragma unroll
        for (int ks = 0; ks < 2; ks++) {
            uint32_t kb = ks * 32;
            uint32_t af[4][4], bf[8][2];
            LDSM4(af[0][0], af[0][1], af[0][2], af[0][3], bufbase + aoffB[0] + kb);
            LDSM4(af[1][0], af[1][1], af[1][2], af[1][3], bufbase + aoffB[1] + kb);
            LDSM4(af[2][0], af[2][1], af[2][2], af[2][3], bufbase + aoffB[2] + kb);
            LDSM4(af[3][0], af[3][1], af[3][2], af[3][3], bufbase + aoffB[3] + kb);
            LDSM4(bf[0][0], bf[0][1], bf[1][0], bf[1][1], bufbase + boffB[0] + kb);
            LDSM4(bf[2][0], bf[2][1], bf[3][0], bf[3][1], bufbase + boffB[1] + kb);
            LDSM4(bf[4][0], bf[4][1], bf[5][0], bf[5][1], bufbase + boffB[2] + kb);
            LDSM4(bf[6][0], bf[6][1], bf[7][0], bf[7][1], bufbase + boffB[3] + kb);
            #pragma unroll
            for (int mt = 0; mt < 4; mt++)
                #pragma unroll
                for (int nt = 0; nt < 8; nt++)
                    mma1688(acc[mt][nt], af[mt], bf[nt]);
        }
        // stage chunk i+1 into the other buffer (LDGs have landed)
        if (i + 1 < NC) {
            uint32_t* base = dsm + ((i + 1) & 1) * 2 * SBUF;
            uint32_t* dA0 = base + ro0;
            uint32_t* dA1 = base + ro1;
            uint32_t* dB0 = dA0 + SBUF;
            uint32_t* dB1 = dA1 + SBUF;
            #pragma unroll
            for (int q = 0; q < 4; q++) {
                *(uint4*)(dA0 + q * 4) = pa[q];
                *(uint4*)(dA1 + q * 4) = pa[q + 4];
                *(uint4*)(dB0 + q * 4) = pb[q];
                *(uint4*)(dB1 + q * 4) = pb[q + 4];
            }
        }
        // ks 2..3
        #pragma unroll
        for (int ks = 2; ks < 4; ks++) {
            uint32_t kb = ks * 32;
            uint32_t af[4][4], bf[8][2];
            LDSM4(af[0][0], af[0][1], af[0][2], af[0][3], bufbase + aoffB[0] + kb);
            LDSM4(af[1][0], af[1][1], af[1][2], af[1][3], bufbase + aoffB[1] + kb);
            LDSM4(af[2][0], af[2][1], af[2][2], af[2][3], bufbase + aoffB[2] + kb);
            LDSM4(af[3][0], af[3][1], af[3][2], af[3][3], bufbase + aoffB[3] + kb);
            LDSM4(bf[0][0], bf[0][1], bf[1][0], bf[1][1], bufbase + boffB[0] + kb);
            LDSM4(bf[2][0], bf[2][1], bf[3][0], bf[3][1], bufbase + boffB[1] + kb);
            LDSM4(bf[4][0], bf[4][1], bf[5][0], bf[5][1], bufbase + boffB[2] + kb);
            LDSM4(bf[6][0], bf[6][1], bf[7][0], bf[7][1], bufbase + boffB[3] + kb);
            #pragma unroll
            for (int mt = 0; mt < 4; mt++)
                #pragma unroll
                for (int nt = 0; nt < 8; nt++)
                    mma1688(acc[mt][nt], af[mt], bf[nt]);
        }
        __syncthreads();
    }

    // epilogue
    #pragma unroll
    for (int mt = 0; mt < 4; mt++) {
        #pragma unroll
        for (int nt = 0; nt < 8; nt++) {
            int col = blockIdx.x * 128 + wn * 64 + nt * 8 + 2 * tg;
            float2 bb = *(const float2*)(bias + col);
            #pragma unroll
            for (int h = 0; h < 2; h++) {
                int row = blockIdx.y * 128 + wm * 64 + mt * 16 + gq + h * 8;
                size_t off = (size_t)row * Mout + col;
                float2 o;
                o.x = acc[mt][nt][2 * h + 0] + bb.x;
                o.y = acc[mt][nt][2 * h + 1] + bb.y;
                if (EPI == 1) { o.x = gelu_f(o.x); o.y = gelu_f(o.y); }
                if (EPI == 2) {
                    float2 rr = *(const float2*)(res + off);
                    o.x += rr.x; o.y += rr.y;
                }
                if (EPI == 1 || EPI == 3) {
                    o.x = __uint_as_float(f2tf32(o.x));
                    o.y = __uint_as_float(f2tf32(o.y));
                }
                *(float2*)(C + off) = o;
            }
        }
    }
}

// ---------------- tensor-core flash attention (tf32) ------------------------
// 128 queries/CTA, 8 warps x 16 queries, key tiles 64. 2 CTAs/SM.
#define ASTR 68
#define VSTR 72

__device__ __forceinline__ void quad_permute(uint32_t p0, uint32_t p1, int lane,
                                             uint32_t& a_lo, uint32_t& a_hi) {
    int tg = lane & 3;
    int base = lane & ~3;
    int l1 = base + (tg >> 1);
    int l2 = base + 2 + (tg >> 1);
    uint32_t s0a = __shfl_sync(0xffffffffu, p0, l1);
    uint32_t s1a = __shfl_sync(0xffffffffu, p1, l1);
    uint32_t s0b = __shfl_sync(0xffffffffu, p0, l2);
    uint32_t s1b = __shfl_sync(0xffffffffu, p1, l2);
    a_lo = (tg & 1) ? s1a : s0a;
    a_hi = (tg & 1) ? s1b : s0b;
}

__global__ __launch_bounds__(256, 2)
void attn_tc() {
    __shared__ uint32_t sK[64 * ASTR];
    __shared__ uint32_t sV[64 * VSTR];
    __shared__ float sPad[64];

    int qt = (gridDim.x - 1) - blockIdx.x;  // longest CTAs first
    int bh = blockIdx.y;
    int b = bh >> 4, h = bh & 15;
    int tid = threadIdx.x;
    int lane = tid & 31;
    int w = tid >> 5;
    int gq = lane >> 2, tg = lane & 3;
    int qabs0 = qt * 128 + w * 16;

    uint32_t koffB[4];
    #pragma unroll
    for (int p = 0; p < 4; p++)
        koffB[p] = ((p * 16 + ((lane >> 4) << 3) + (lane & 7)) * ASTR
                    + (((lane >> 3) & 1) << 2)) * 4;
    uint32_t skb = smem_u32(sK);

    uint32_t qa[8][4];
    const float* Qb = g_qkv + ((size_t)(b * SD) + qabs0) * QKVD + h * DHH;
    #pragma unroll
    for (int ks = 0; ks < 8; ks++) {
        qa[ks][0] = __float_as_uint(Qb[(size_t)gq * QKVD + ks * 8 + tg]);
        qa[ks][1] = __float_as_uint(Qb[(size_t)(gq + 8) * QKVD + ks * 8 + tg]);
        qa[ks][2] = __float_as_uint(Qb[(size_t)gq * QKVD + ks * 8 + tg + 4]);
        qa[ks][3] = __float_as_uint(Qb[(size_t)(gq + 8) * QKVD + ks * 8 + tg + 4]);
    }

    float m0 = -1e30f, m1 = -1e30f, l0 = 0.0f, l1 = 0.0f;
    float Oa[8][4];
    #pragma unroll
    for (int nt = 0; nt < 8; nt++)
        #pragma unroll
        for (int c = 0; c < 4; c++) Oa[nt][c] = 0.0f;

    int lr = tid >> 2;
    int lc = (tid & 3) * 16;

    int KBMAX = 2 * qt + 1;
    for (int kb = 0; kb <= KBMAX; kb++) {
        size_t gb = ((size_t)(b * SD) + kb * 64 + lr) * QKVD + h * DHH + lc;
        uint32_t* kRow = sK + lr * ASTR + lc;
        uint32_t* vRow = sV + lr * VSTR + lc;
        #pragma unroll
        for (int q = 0; q < 4; q++) {
            *(uint4*)(kRow + q * 4) = *(const uint4*)(g_qkv + gb + 1024 + q * 4);
            *(uint4*)(vRow + q * 4) = *(const uint4*)(g_qkv + gb + 2048 + q * 4);
        }
        if (tid < 64) sPad[tid] = g_pad[(size_t)b * SD + kb * 64 + tid];
        __syncthreads();

        if (kb * 64 <= qabs0 + 15) {
            float sv[8][4];
            #pragma unroll
            for (int nt = 0; nt < 8; nt++)
                #pragma unroll
                for (int c = 0; c < 4; c++) sv[nt][c] = 0.0f;
            #pragma unroll
            for (int ks = 0; ks < 8; ks++) {
                uint32_t kf[8][2];
                uint32_t kbo = ks * 32;
                LDSM4(kf[0][0], kf[0][1], kf[1][0], kf[1][1], skb + koffB[0] + kbo);
                LDSM4(kf[2][0], kf[2][1], kf[3][0], kf[3][1], skb + koffB[1] + kbo);
                LDSM4(kf[4][0], kf[4][1], kf[5][0], kf[5][1], skb + koffB[2] + kbo);
                LDSM4(kf[6][0], kf[6][1], kf[7][0], kf[7][1], skb + koffB[3] + kbo);
                #pragma unroll
                for (int nt = 0; nt < 8; nt++)
                    mma1688(sv[nt], qa[ks], kf[nt]);
            }
            int q0 = qabs0 + gq, q1 = q0 + 8;
            float mx0 = -1e30f, mx1 = -1e30f;
            #pragma unroll
            for (int nt = 0; nt < 8; nt++) {
                int kc = kb * 64 + nt * 8 + 2 * tg;
                float pad0 = sPad[nt * 8 + 2 * tg];
                float pad1 = sPad[nt * 8 + 2 * tg + 1];
                sv[nt][0] = sv[nt][0] * 0.125f + pad0 + ((kc     > q0) ? NEGV : 0.0f);
                sv[nt][1] = sv[nt][1] * 0.125f + pad1 + ((kc + 1 > q0) ? NEGV : 0.0f);
                sv[nt][2] = sv[nt][2] * 0.125f + pad0 + ((kc     > q1) ? NEGV : 0.0f);
                sv[nt][3] = sv[nt][3] * 0.125f + pad1 + ((kc + 1 > q1) ? NEGV : 0.0f);
                mx0 = fmaxf(mx0, fmaxf(sv[nt][0], sv[nt][1]));
                mx1 = fmaxf(mx1, fmaxf(sv[nt][2], sv[nt][3]));
            }
            mx0 = fmaxf(mx0, __shfl_xor_sync(0xffffffffu, mx0, 1));
            mx0 = fmaxf(mx0, __shfl_xor_sync(0xffffffffu, mx0, 2));
            mx1 = fmaxf(mx1, __shfl_xor_sync(0xffffffffu, mx1, 1));
            mx1 = fmaxf(mx1, __shfl_xor_sync(0xffffffffu, mx1, 2));
            float mn0 = fmaxf(m0, mx0), mn1 = fmaxf(m1, mx1);
            float cr0 = __expf(m0 - mn0), cr1 = __expf(m1 - mn1);
            m0 = mn0; m1 = mn1;

            float rs0 = 0.0f, rs1 = 0.0f;
            #pragma unroll
            for (int nt = 0; nt < 8; nt++) {
                float p0 = __expf(sv[nt][0] - mn0);
                float p1 = __expf(sv[nt][1] - mn0);
                float p2 = __expf(sv[nt][2] - mn1);
                float p3 = __expf(sv[nt][3] - mn1);
                rs0 += p0 + p1; rs1 += p2 + p3;
                uint32_t w0, w1c, w2, w3;
                quad_permute(f2tf32(p0), f2tf32(p1), lane, w0, w2);
                quad_permute(f2tf32(p2), f2tf32(p3), lane, w1c, w3);
                sv[nt][0] = __uint_as_float(w0);
                sv[nt][1] = __uint_as_float(w1c);
                sv[nt][2] = __uint_as_float(w2);
                sv[nt][3] = __uint_as_float(w3);
            }
            rs0 += __shfl_xor_sync(0xffffffffu, rs0, 1);
            rs0 += __shfl_xor_sync(0xffffffffu, rs0, 2);
            rs1 += __shfl_xor_sync(0xffffffffu, rs1, 1);
            rs1 += __shfl_xor_sync(0xffffffffu, rs1, 2);
            l0 = l0 * cr0 + rs0;
            l1 = l1 * cr1 + rs1;
            #pragma unroll
            for (int nt = 0; nt < 8; nt++) {
                Oa[nt][0] *= cr0; Oa[nt][1] *= cr0;
                Oa[nt][2] *= cr1; Oa[nt][3] *= cr1;
            }
            #pragma unroll
            for (int ks = 0; ks < 8; ks++) {
                uint32_t pf[4] = { __float_as_uint(sv[ks][0]), __float_as_uint(sv[ks][1]),
                                   __float_as_uint(sv[ks][2]), __float_as_uint(sv[ks][3]) };
                #pragma unroll
                for (int nt = 0; nt < 8; nt++) {
                    const uint32_t* vp = sV + (ks * 8 + tg) * VSTR + nt * 8 + gq;
                    uint32_t bv[2] = { vp[0], vp[4 * VSTR] };
                    mma1688(Oa[nt], pf, bv);
                }
            }
        }
        __syncthreads();
    }

    float inv0 = 1.0f / l0, inv1 = 1.0f / l1;
    size_t o0 = ((size_t)(b * SD) + qabs0 + gq) * DD + h * DHH + 2 * tg;
    size_t o1 = o0 + (size_t)8 * DD;
    #pragma unroll
    for (int nt = 0; nt < 8; nt++) {
        *(float2*)(g_att + o0 + nt * 8) =
            make_float2(__uint_as_float(f2tf32(Oa[nt][0] * inv0)),
                        __uint_as_float(f2tf32(Oa[nt][1] * inv0)));
        *(float2*)(g_att + o1 + nt * 8) =
            make_float2(__uint_as_float(f2tf32(Oa[nt][2] * inv1)),
                        __uint_as_float(f2tf32(Oa[nt][3] * inv1)));
    }
}

// ---------------- launch --------------------------------------------------
extern "C" void kernel_launch(void* const* d_in, const int* in_sizes, int n_in,
                              void* d_out, int out_size) {
    const int*   tokens = (const int*)  d_in[0];
    const float* emb    = (const float*)d_in[1];
    const float* pos    = (const float*)d_in[2];
    const float* ln1_g  = (const float*)d_in[3];
    const float* ln1_b  = (const float*)d_in[4];
    const float* ln2_g  = (const float*)d_in[5];
    const float* ln2_b  = (const float*)d_in[6];
    const float* ln3_g  = (const float*)d_in[7];
    const float* ln3_b  = (const float*)d_in[8];
    const float* Wq     = (const float*)d_in[9];
    const float* bq     = (const float*)d_in[10];
    const float* Wk     = (const float*)d_in[11];
    const float* bk     = (const float*)d_in[12];
    const float* Wv     = (const float*)d_in[13];
    const float* bv     = (const float*)d_in[14];
    const float* Wo     = (const float*)d_in[15];
    const float* bo     = (const float*)d_in[16];
    const float* W1     = (const float*)d_in[17];
    const float* b1     = (const float*)d_in[18];
    const float* W2     = (const float*)d_in[19];
    const float* b2     = (const float*)d_in[20];
    float* out = (float*)d_out;

    float *xp, *xtp, *qkvp, *attp, *aop, *xnp, *hp;
    float *wqkvp, *bqkvp, *wop, *w1p, *w2p;
    cudaGetSymbolAddress((void**)&xp,    g_x);
    cudaGetSymbolAddress((void**)&xtp,   g_xt);
    cudaGetSymbolAddress((void**)&qkvp,  g_qkv);
    cudaGetSymbolAddress((void**)&attp,  g_att);
    cudaGetSymbolAddress((void**)&aop,   g_ao);
    cudaGetSymbolAddress((void**)&xnp,   g_xn);
    cudaGetSymbolAddress((void**)&hp,    g_h);
    cudaGetSymbolAddress((void**)&wqkvp, g_wqkv);
    cudaGetSymbolAddress((void**)&bqkvp, g_bqkv);
    cudaGetSymbolAddress((void**)&wop,   g_wo);
    cudaGetSymbolAddress((void**)&w1p,   g_w1);
    cudaGetSymbolAddress((void**)&w2p,   g_w2);

    static bool attr_done = false;
    if (!attr_done) {
        cudaFuncSetAttribute(tc_gemm<0>, cudaFuncAttributeMaxDynamicSharedMemorySize, GEMM_SMEM);
        cudaFuncSetAttribute(tc_gemm<1>, cudaFuncAttributeMaxDynamicSharedMemorySize, GEMM_SMEM);
        cudaFuncSetAttribute(tc_gemm<2>, cudaFuncAttributeMaxDynamicSharedMemorySize, GEMM_SMEM);
        cudaFuncSetAttribute(tc_gemm<3>, cudaFuncAttributeMaxDynamicSharedMemorySize, GEMM_SMEM);
        attr_done = true;
    }

    dim3 tb(32, 8);
    embed_ln_k<<<NR / 8, 256>>>(tokens, emb, pos, ln1_g, ln1_b);
    transpose_qkvo_k<<<dim3(DD / 32, DD / 32, 4), tb>>>(Wq, Wk, Wv, Wo, bq, bk, bv);
    transpose_w12_k<<<dim3(FFD / 32, DD / 32, 2), tb>>>(W1, W2);

    // fused QKV projection (tf32-rounded output)
    tc_gemm<3><<<dim3(QKVD / 128, NR / 128), 128, GEMM_SMEM>>>(xtp, wqkvp, bqkvp, qkvp, DD, QKVD, nullptr);

    attn_tc<<<dim3(SD / 128, BD * HH), 256>>>();

    tc_gemm<0><<<dim3(DD / 128, NR / 128), 128, GEMM_SMEM>>>(attp, wop, bo, aop, DD, DD, nullptr);
    ln23_k<<<NR / 8, 256>>>(ln2_g, ln2_b, ln3_g, ln3_b);

    tc_gemm<1><<<dim3(FFD / 128, NR / 128), 128, GEMM_SMEM>>>(xnp, w1p, b1, hp, DD, FFD, nullptr);
    tc_gemm<2><<<dim3(DD / 128, NR / 128), 128, GEMM_SMEM>>>(hp, w2p, b2, out, FFD, DD, xp);
}